// round 2
// baseline (speedup 1.0000x reference)
#include <cuda_runtime.h>
#include <math.h>

#define NV 6144
#define NF 512
#define NH 256
#define NC 16

// ---------------- scratch (device globals, no allocation) ----------------
__device__ float g_adj[(size_t)NV * NV];   // combined adjacency
__device__ float g_att[(size_t)NV * NV];   // A_tilde / attention (in-place softmax)
__device__ float g_z123[NV * 15];
__device__ float g_nzT[3][NV];             // transposed gates for column-broadcast
__device__ float g_xw[NV * NH];
__device__ float g_h[NV * NH];
__device__ float g_Q[NV * NH];
__device__ float g_K[NV * NH];
__device__ float g_V[NV * NH];
__device__ float g_X[NV * NH];
__device__ float g_u[NV * NC];
__device__ float g_z[NV * NC];

// ---------------- gating pass ----------------
__global__ void init_z123_kernel(const float* __restrict__ b1,
                                 const float* __restrict__ b2,
                                 const float* __restrict__ b3) {
    int idx = blockIdx.x * blockDim.x + threadIdx.x;
    if (idx < NV * 15) {
        int f = idx % 15;
        int m = f / 5;
        const float* b = (m == 0) ? b1 : (m == 1) ? b2 : b3;
        g_z123[idx] = b[f % 5];
    }
}

// z_m = adj_m @ W_at_m  (accumulated atomically on top of bias)
// grid (24 rowblocks, 24 jchunks, 3 matrices), 256 threads (8 warps x 32 rows)
__global__ __launch_bounds__(256) void gates_kernel(
    const float* __restrict__ a0, const float* __restrict__ a1, const float* __restrict__ a2,
    const float* __restrict__ W1, const float* __restrict__ W2, const float* __restrict__ W3) {
    int m = blockIdx.z;
    const float* A = (m == 0) ? a0 : (m == 1) ? a1 : a2;
    const float* W = (m == 0) ? W1 : (m == 1) ? W2 : W3;
    int warp = threadIdx.x >> 5;
    int lane = threadIdx.x & 31;
    int jbase = blockIdx.y * 256;
    int row0 = blockIdx.x * 256 + warp * 32;

    float w[8][5];
#pragma unroll
    for (int k = 0; k < 8; k++) {
        int j = jbase + k * 32 + lane;
#pragma unroll
        for (int f = 0; f < 5; f++) w[k][f] = W[j * 5 + f];
    }

    for (int r = 0; r < 32; r++) {
        int i = row0 + r;
        const float* arow = A + (size_t)i * NV + jbase;
        float ac0 = 0.f, ac1 = 0.f, ac2 = 0.f, ac3 = 0.f, ac4 = 0.f;
#pragma unroll
        for (int k = 0; k < 8; k++) {
            float a = arow[k * 32 + lane];
            ac0 = fmaf(a, w[k][0], ac0);
            ac1 = fmaf(a, w[k][1], ac1);
            ac2 = fmaf(a, w[k][2], ac2);
            ac3 = fmaf(a, w[k][3], ac3);
            ac4 = fmaf(a, w[k][4], ac4);
        }
#pragma unroll
        for (int off = 16; off > 0; off >>= 1) {
            ac0 += __shfl_xor_sync(0xffffffffu, ac0, off);
            ac1 += __shfl_xor_sync(0xffffffffu, ac1, off);
            ac2 += __shfl_xor_sync(0xffffffffu, ac2, off);
            ac3 += __shfl_xor_sync(0xffffffffu, ac3, off);
            ac4 += __shfl_xor_sync(0xffffffffu, ac4, off);
        }
        if (lane == 0) {
            float* zp = &g_z123[i * 15 + m * 5];
            atomicAdd(zp + 0, ac0);
            atomicAdd(zp + 1, ac1);
            atomicAdd(zp + 2, ac2);
            atomicAdd(zp + 3, ac3);
            atomicAdd(zp + 4, ac4);
        }
    }
}

// z4 = z123 @ W_agg + b_agg ; nz = softmax(z4). Writes transposed gates + nj output.
__global__ void nz_kernel(const float* __restrict__ Wagg, const float* __restrict__ bagg,
                          float* __restrict__ out) {
    int i = blockIdx.x * blockDim.x + threadIdx.x;
    if (i >= NV) return;
    float zi[15];
#pragma unroll
    for (int f = 0; f < 15; f++) zi[f] = g_z123[i * 15 + f];
    float z4[3];
#pragma unroll
    for (int c = 0; c < 3; c++) {
        float s = bagg[c];
#pragma unroll
        for (int f = 0; f < 15; f++) s = fmaf(zi[f], Wagg[f * 3 + c], s);
        z4[c] = s;
    }
    float mx = fmaxf(z4[0], fmaxf(z4[1], z4[2]));
    float e0 = __expf(z4[0] - mx);
    float e1 = __expf(z4[1] - mx);
    float e2 = __expf(z4[2] - mx);
    float inv = 1.0f / (e0 + e1 + e2);
    float p0 = e0 * inv, p1 = e1 * inv, p2 = e2 * inv;
    g_nzT[0][i] = p0;
    g_nzT[1][i] = p1;
    g_nzT[2][i] = p2;
    out[NV * NC + i * 3 + 0] = p0;
    out[NV * NC + i * 3 + 1] = p1;
    out[NV * NC + i * 3 + 2] = p2;
}

// adj[i,j] = nz[j,0]*a0[i,j] + nz[j,1]*a1[i,j] + nz[j,2]*a2[i,j]  (column broadcast)
__global__ void combine_kernel(const float4* __restrict__ a0, const float4* __restrict__ a1,
                               const float4* __restrict__ a2) {
    size_t t = (size_t)blockIdx.x * blockDim.x + threadIdx.x;
    const size_t total = (size_t)NV * NV / 4;
    if (t >= total) return;
    int j4 = (int)(t % (NV / 4));
    const float4* n0 = (const float4*)g_nzT[0];
    const float4* n1 = (const float4*)g_nzT[1];
    const float4* n2 = (const float4*)g_nzT[2];
    float4 v0 = a0[t], v1 = a1[t], v2 = a2[t];
    float4 w0 = n0[j4], w1 = n1[j4], w2 = n2[j4];
    float4 r;
    r.x = fmaf(w0.x, v0.x, fmaf(w1.x, v1.x, w2.x * v2.x));
    r.y = fmaf(w0.y, v0.y, fmaf(w1.y, v1.y, w2.y * v2.y));
    r.z = fmaf(w0.z, v0.z, fmaf(w1.z, v1.z, w2.z * v2.z));
    r.w = fmaf(w0.w, v0.w, fmaf(w1.w, v1.w, w2.w * v2.w));
    ((float4*)g_adj)[t] = r;
}

// ---------------- generic fp32 tiled GEMM  C[M,Nc] = A[M,Kc] (@) B ----------------
// BM=128, BN=128, BK=16, 256 threads, 8x8 register tile.
#define EPI_NONE 0
#define EPI_BIAS 1
#define EPI_BIAS_RELU 2
#define EPI_RELU 3
#define EPI_MUL 4

template <int EPI, bool TRANSB>
__global__ __launch_bounds__(256) void gemm_kernel(
    const float* __restrict__ A, const float* __restrict__ B, float* __restrict__ C,
    int M, int Nc, int Kc, int lda, int ldb,
    const float* __restrict__ bias, const float* __restrict__ elem) {
    __shared__ float As[16][128];
    __shared__ float Bs[16][128];
    int tid = threadIdx.x;
    int bm = blockIdx.y * 128;
    int bn = blockIdx.x * 128;
    int tx = tid & 15;
    int ty = tid >> 4;
    float acc[8][8] = {};

    int arow = tid >> 1;
    int akk = (tid & 1) * 8;

    for (int k0 = 0; k0 < Kc; k0 += 16) {
        // stage A (transposed into smem: As[kk][row])
        {
            const float* ap = A + (size_t)(bm + arow) * lda + k0 + akk;
            float4 p0 = *(const float4*)ap;
            float4 p1 = *(const float4*)(ap + 4);
            As[akk + 0][arow] = p0.x;
            As[akk + 1][arow] = p0.y;
            As[akk + 2][arow] = p0.z;
            As[akk + 3][arow] = p0.w;
            As[akk + 4][arow] = p1.x;
            As[akk + 5][arow] = p1.y;
            As[akk + 6][arow] = p1.z;
            As[akk + 7][arow] = p1.w;
        }
        if (!TRANSB) {
            int bkk = tid >> 4;
            int bcol = (tid & 15) * 8;
            const float* bp = B + (size_t)(k0 + bkk) * ldb + bn + bcol;
            float4 zz = make_float4(0.f, 0.f, 0.f, 0.f);
            float4 b0 = (bn + bcol < Nc) ? *(const float4*)bp : zz;
            float4 b1 = (bn + bcol + 4 < Nc) ? *(const float4*)(bp + 4) : zz;
            *(float4*)&Bs[bkk][bcol] = b0;
            *(float4*)&Bs[bkk][bcol + 4] = b1;
        } else {
            int bcol = tid >> 1;
            int bkk = (tid & 1) * 8;
            const float* bp = B + (size_t)(bn + bcol) * ldb + k0 + bkk;
            float4 p0 = *(const float4*)bp;
            float4 p1 = *(const float4*)(bp + 4);
            Bs[bkk + 0][bcol] = p0.x;
            Bs[bkk + 1][bcol] = p0.y;
            Bs[bkk + 2][bcol] = p0.z;
            Bs[bkk + 3][bcol] = p0.w;
            Bs[bkk + 4][bcol] = p1.x;
            Bs[bkk + 5][bcol] = p1.y;
            Bs[bkk + 6][bcol] = p1.z;
            Bs[bkk + 7][bcol] = p1.w;
        }
        __syncthreads();
#pragma unroll
        for (int kk = 0; kk < 16; kk++) {
            float a[8], b[8];
            *(float4*)&a[0] = *(float4*)&As[kk][ty * 8];
            *(float4*)&a[4] = *(float4*)&As[kk][ty * 8 + 4];
            *(float4*)&b[0] = *(float4*)&Bs[kk][tx * 8];
            *(float4*)&b[4] = *(float4*)&Bs[kk][tx * 8 + 4];
#pragma unroll
            for (int i = 0; i < 8; i++)
#pragma unroll
                for (int j = 0; j < 8; j++) acc[i][j] = fmaf(a[i], b[j], acc[i][j]);
        }
        __syncthreads();
    }

#pragma unroll
    for (int i = 0; i < 8; i++) {
        int row = bm + ty * 8 + i;
        size_t base = (size_t)row * Nc;
#pragma unroll
        for (int j = 0; j < 8; j++) {
            int col = bn + tx * 8 + j;
            if (col < Nc) {
                float v = acc[i][j];
                if (EPI == EPI_BIAS || EPI == EPI_BIAS_RELU) v += bias[col];
                if (EPI == EPI_BIAS_RELU || EPI == EPI_RELU) v = fmaxf(v, 0.f);
                if (EPI == EPI_MUL) v *= elem[base + col];
                C[base + col] = v;
            }
        }
    }
}

// ---------------- row softmax over 6144-wide rows (in place) ----------------
__global__ __launch_bounds__(256) void softmax_rows_kernel(float* __restrict__ buf) {
    int row = blockIdx.x;
    float* p = buf + (size_t)row * NV;
    int tid = threadIdx.x;
    int lane = tid & 31, wid = tid >> 5;
    __shared__ float red[8];
    __shared__ float red2[8];

    float v[24];
    float mx = -3.0e38f;
#pragma unroll
    for (int t = 0; t < 24; t++) {
        v[t] = p[t * 256 + tid];
        mx = fmaxf(mx, v[t]);
    }
#pragma unroll
    for (int off = 16; off > 0; off >>= 1) mx = fmaxf(mx, __shfl_xor_sync(0xffffffffu, mx, off));
    if (lane == 0) red[wid] = mx;
    __syncthreads();
    float rowmax = red[0];
#pragma unroll
    for (int w = 1; w < 8; w++) rowmax = fmaxf(rowmax, red[w]);

    float s = 0.f;
#pragma unroll
    for (int t = 0; t < 24; t++) {
        v[t] = __expf(v[t] - rowmax);
        s += v[t];
    }
#pragma unroll
    for (int off = 16; off > 0; off >>= 1) s += __shfl_xor_sync(0xffffffffu, s, off);
    if (lane == 0) red2[wid] = s;
    __syncthreads();
    float tot = 0.f;
#pragma unroll
    for (int w = 0; w < 8; w++) tot += red2[w];
    float inv = 1.0f / tot;
#pragma unroll
    for (int t = 0; t < 24; t++) p[t * 256 + tid] = v[t] * inv;
}

// ---------------- final stage: z = adj @ u + b_g2 (N=16, k-split) ----------------
__global__ void init_z_kernel(const float* __restrict__ bg2) {
    int idx = blockIdx.x * blockDim.x + threadIdx.x;
    if (idx < NV * NC) g_z[idx] = bg2[idx % NC];
}

__global__ __launch_bounds__(256) void gemm_n16_ksplit(const float* __restrict__ A, int lda,
                                                       const float* __restrict__ Bm,
                                                       float* __restrict__ C, int Kchunk) {
    __shared__ float As[64][128];
    __shared__ float Bs[64][16];
    int tid = threadIdx.x;
    int bm = blockIdx.x * 128;
    int k0base = blockIdx.y * Kchunk;
    int col = tid & 15;
    int rowg = tid >> 4;
    float acc[8] = {};

    int arow = tid >> 1;
    int ak0 = (tid & 1) * 32;
    int bk = tid >> 2;
    int bc4 = (tid & 3) * 4;

    for (int k0 = k0base; k0 < k0base + Kchunk; k0 += 64) {
        float4 bv = *(const float4*)(Bm + (size_t)(k0 + bk) * 16 + bc4);
        *(float4*)&Bs[bk][bc4] = bv;
        const float* ap = A + (size_t)(bm + arow) * lda + k0 + ak0;
#pragma unroll
        for (int c = 0; c < 8; c++) {
            float4 av = *(const float4*)(ap + 4 * c);
            As[ak0 + 4 * c + 0][arow] = av.x;
            As[ak0 + 4 * c + 1][arow] = av.y;
            As[ak0 + 4 * c + 2][arow] = av.z;
            As[ak0 + 4 * c + 3][arow] = av.w;
        }
        __syncthreads();
#pragma unroll 8
        for (int kk = 0; kk < 64; kk++) {
            float b = Bs[kk][col];
#pragma unroll
            for (int i = 0; i < 8; i++) acc[i] = fmaf(As[kk][rowg * 8 + i], b, acc[i]);
        }
        __syncthreads();
    }
#pragma unroll
    for (int i = 0; i < 8; i++)
        atomicAdd(&C[(size_t)(bm + rowg * 8 + i) * NC + col], acc[i]);
}

__global__ void softmax16_kernel(const float* __restrict__ z, float* __restrict__ out) {
    int i = blockIdx.x * blockDim.x + threadIdx.x;
    if (i >= NV) return;
    float v[NC];
    float mx = -3.0e38f;
#pragma unroll
    for (int c = 0; c < NC; c++) {
        v[c] = z[i * NC + c];
        mx = fmaxf(mx, v[c]);
    }
    float s = 0.f;
#pragma unroll
    for (int c = 0; c < NC; c++) {
        v[c] = __expf(v[c] - mx);
        s += v[c];
    }
    float inv = 1.0f / s;
#pragma unroll
    for (int c = 0; c < NC; c++) out[i * NC + c] = v[c] * inv;
}

// ---------------- host orchestration ----------------
extern "C" void kernel_launch(void* const* d_in, const int* in_sizes, int n_in,
                              void* d_out, int out_size) {
    const float* adj0 = (const float*)d_in[0];
    const float* adj1 = (const float*)d_in[1];
    const float* adj2 = (const float*)d_in[2];
    const float* x = (const float*)d_in[3];
    const float* W_at1 = (const float*)d_in[4];
    const float* b_at1 = (const float*)d_in[5];
    const float* W_at2 = (const float*)d_in[6];
    const float* b_at2 = (const float*)d_in[7];
    const float* W_at3 = (const float*)d_in[8];
    const float* b_at3 = (const float*)d_in[9];
    const float* W_agg = (const float*)d_in[10];
    const float* b_agg = (const float*)d_in[11];
    const float* W_g1 = (const float*)d_in[12];
    const float* b_g1 = (const float*)d_in[13];
    const float* W_g2 = (const float*)d_in[14];
    const float* b_g2 = (const float*)d_in[15];
    const float* W_q = (const float*)d_in[16];
    const float* b_q = (const float*)d_in[17];
    const float* W_k = (const float*)d_in[18];
    const float* b_k = (const float*)d_in[19];
    const float* W_v = (const float*)d_in[20];
    const float* b_v = (const float*)d_in[21];
    float* out = (float*)d_out;

    void* p;
    cudaGetSymbolAddress(&p, g_adj);   float* adjS = (float*)p;
    cudaGetSymbolAddress(&p, g_att);   float* attS = (float*)p;
    cudaGetSymbolAddress(&p, g_xw);    float* xwS = (float*)p;
    cudaGetSymbolAddress(&p, g_h);     float* hS = (float*)p;
    cudaGetSymbolAddress(&p, g_Q);     float* QS = (float*)p;
    cudaGetSymbolAddress(&p, g_K);     float* KS = (float*)p;
    cudaGetSymbolAddress(&p, g_V);     float* VS = (float*)p;
    cudaGetSymbolAddress(&p, g_X);     float* XS = (float*)p;
    cudaGetSymbolAddress(&p, g_u);     float* uS = (float*)p;
    cudaGetSymbolAddress(&p, g_z);     float* zS = (float*)p;

    // 1. gating
    init_z123_kernel<<<(NV * 15 + 255) / 256, 256>>>(b_at1, b_at2, b_at3);
    gates_kernel<<<dim3(24, 24, 3), 256>>>(adj0, adj1, adj2, W_at1, W_at2, W_at3);
    nz_kernel<<<(NV + 255) / 256, 256>>>(W_agg, b_agg, out);

    // 2. combined adjacency
    combine_kernel<<<(unsigned)((size_t)NV * NV / 4 / 256), 256>>>(
        (const float4*)adj0, (const float4*)adj1, (const float4*)adj2);

    // 3. xw = x @ W_g1
    gemm_kernel<EPI_NONE, false><<<dim3(2, 48), 256>>>(x, W_g1, xwS, NV, NH, NF, NF, NH,
                                                       nullptr, nullptr);
    // 4. h = relu(adj @ xw + b_g1)
    gemm_kernel<EPI_BIAS_RELU, false><<<dim3(2, 48), 256>>>(adjS, xwS, hS, NV, NH, NV, NV, NH,
                                                            b_g1, nullptr);
    // 5. Q, K, V
    gemm_kernel<EPI_BIAS, false><<<dim3(2, 48), 256>>>(hS, W_q, QS, NV, NH, NH, NH, NH, b_q, nullptr);
    gemm_kernel<EPI_BIAS, false><<<dim3(2, 48), 256>>>(hS, W_k, KS, NV, NH, NH, NH, NH, b_k, nullptr);
    gemm_kernel<EPI_BIAS, false><<<dim3(2, 48), 256>>>(hS, W_v, VS, NV, NH, NH, NH, NH, b_v, nullptr);

    // 6. A_tilde = adj * (Q @ K^T)
    gemm_kernel<EPI_MUL, true><<<dim3(48, 48), 256>>>(QS, KS, attS, NV, NV, NH, NH, NH,
                                                      nullptr, adjS);
    // 7. attention = softmax(A_tilde, axis=1)   (gcn_norm == identity to ~1e-7)
    softmax_rows_kernel<<<NV, 256>>>(attS);

    // 8. X_tilde = relu(attention @ V)
    gemm_kernel<EPI_RELU, false><<<dim3(2, 48), 256>>>(attS, VS, XS, NV, NH, NV, NV, NH,
                                                       nullptr, nullptr);
    // 9. u = X_tilde @ W_g2
    gemm_kernel<EPI_NONE, false><<<dim3(1, 48), 256>>>(XS, W_g2, uS, NV, NC, NH, NH, NC,
                                                       nullptr, nullptr);
    // 10. z = adj @ u + b_g2 (k-split, atomic accumulate)
    init_z_kernel<<<(NV * NC + 255) / 256, 256>>>(b_g2);
    gemm_n16_ksplit<<<dim3(48, 8), 256>>>(adjS, NV, uS, zS, NV / 8);

    // 11. out[:, :16] = softmax(z)
    softmax16_kernel<<<(NV + 255) / 256, 256>>>(zS, out);

    (void)in_sizes; (void)n_in; (void)out_size;
}

// round 4
// speedup vs baseline: 1.0726x; 1.0726x over previous
#include <cuda_runtime.h>
#include <math.h>

#define NV 6144
#define NF 512
#define NH 256
#define NC 16

typedef unsigned long long u64;

// ---------------- packed f32x2 helpers (sm_103a FFMA2 path) ----------------
__device__ __forceinline__ u64 pack2(float lo, float hi) {
    u64 r;
    asm("mov.b64 %0, {%1, %2};" : "=l"(r) : "f"(lo), "f"(hi));
    return r;
}
__device__ __forceinline__ void fma2(u64& d, u64 a, u64 b) {
    asm("fma.rn.f32x2 %0, %1, %2, %0;" : "+l"(d) : "l"(a), "l"(b));
}
__device__ __forceinline__ float2 unpack2(u64 v) {
    float2 r;
    asm("mov.b64 {%0, %1}, %2;" : "=f"(r.x), "=f"(r.y) : "l"(v));
    return r;
}

// ---------------- scratch (device globals, no allocation) ----------------
__device__ float g_adj[(size_t)NV * NV];   // combined adjacency
__device__ float g_att[(size_t)NV * NV];   // A_tilde / attention (in-place softmax)
__device__ float g_z123[NV * 15];
__device__ float g_nzT[3][NV];             // transposed gates for column-broadcast
__device__ float g_xw[NV * NH];
__device__ float g_h[NV * NH];
__device__ float g_Q[NV * NH];
__device__ float g_K[NV * NH];
__device__ float g_V[NV * NH];
__device__ float g_X[NV * NH];
__device__ float g_u[NV * NC];
__device__ float g_z[NV * NC];

// ---------------- gating pass ----------------
__global__ void init_z123_kernel(const float* __restrict__ b1,
                                 const float* __restrict__ b2,
                                 const float* __restrict__ b3) {
    int idx = blockIdx.x * blockDim.x + threadIdx.x;
    if (idx < NV * 15) {
        int f = idx % 15;
        int m = f / 5;
        const float* b = (m == 0) ? b1 : (m == 1) ? b2 : b3;
        g_z123[idx] = b[f % 5];
    }
}

// z_m = adj_m @ W_at_m  (accumulated atomically on top of bias)
__global__ __launch_bounds__(256) void gates_kernel(
    const float* __restrict__ a0, const float* __restrict__ a1, const float* __restrict__ a2,
    const float* __restrict__ W1, const float* __restrict__ W2, const float* __restrict__ W3) {
    int m = blockIdx.z;
    const float* A = (m == 0) ? a0 : (m == 1) ? a1 : a2;
    const float* W = (m == 0) ? W1 : (m == 1) ? W2 : W3;
    int warp = threadIdx.x >> 5;
    int lane = threadIdx.x & 31;
    int jbase = blockIdx.y * 256;
    int row0 = blockIdx.x * 256 + warp * 32;

    float w[8][5];
#pragma unroll
    for (int k = 0; k < 8; k++) {
        int j = jbase + k * 32 + lane;
#pragma unroll
        for (int f = 0; f < 5; f++) w[k][f] = W[j * 5 + f];
    }

    for (int r = 0; r < 32; r++) {
        int i = row0 + r;
        const float* arow = A + (size_t)i * NV + jbase;
        float ac0 = 0.f, ac1 = 0.f, ac2 = 0.f, ac3 = 0.f, ac4 = 0.f;
#pragma unroll
        for (int k = 0; k < 8; k++) {
            float a = arow[k * 32 + lane];
            ac0 = fmaf(a, w[k][0], ac0);
            ac1 = fmaf(a, w[k][1], ac1);
            ac2 = fmaf(a, w[k][2], ac2);
            ac3 = fmaf(a, w[k][3], ac3);
            ac4 = fmaf(a, w[k][4], ac4);
        }
#pragma unroll
        for (int off = 16; off > 0; off >>= 1) {
            ac0 += __shfl_xor_sync(0xffffffffu, ac0, off);
            ac1 += __shfl_xor_sync(0xffffffffu, ac1, off);
            ac2 += __shfl_xor_sync(0xffffffffu, ac2, off);
            ac3 += __shfl_xor_sync(0xffffffffu, ac3, off);
            ac4 += __shfl_xor_sync(0xffffffffu, ac4, off);
        }
        if (lane == 0) {
            float* zp = &g_z123[i * 15 + m * 5];
            atomicAdd(zp + 0, ac0);
            atomicAdd(zp + 1, ac1);
            atomicAdd(zp + 2, ac2);
            atomicAdd(zp + 3, ac3);
            atomicAdd(zp + 4, ac4);
        }
    }
}

// z4 = z123 @ W_agg + b_agg ; nz = softmax(z4). Writes transposed gates + nj output.
__global__ void nz_kernel(const float* __restrict__ Wagg, const float* __restrict__ bagg,
                          float* __restrict__ out) {
    int i = blockIdx.x * blockDim.x + threadIdx.x;
    if (i >= NV) return;
    float zi[15];
#pragma unroll
    for (int f = 0; f < 15; f++) zi[f] = g_z123[i * 15 + f];
    float z4[3];
#pragma unroll
    for (int c = 0; c < 3; c++) {
        float s = bagg[c];
#pragma unroll
        for (int f = 0; f < 15; f++) s = fmaf(zi[f], Wagg[f * 3 + c], s);
        z4[c] = s;
    }
    float mx = fmaxf(z4[0], fmaxf(z4[1], z4[2]));
    float e0 = __expf(z4[0] - mx);
    float e1 = __expf(z4[1] - mx);
    float e2 = __expf(z4[2] - mx);
    float inv = 1.0f / (e0 + e1 + e2);
    float p0 = e0 * inv, p1 = e1 * inv, p2 = e2 * inv;
    g_nzT[0][i] = p0;
    g_nzT[1][i] = p1;
    g_nzT[2][i] = p2;
    out[NV * NC + i * 3 + 0] = p0;
    out[NV * NC + i * 3 + 1] = p1;
    out[NV * NC + i * 3 + 2] = p2;
}

// adj[i,j] = nz[j,0]*a0[i,j] + nz[j,1]*a1[i,j] + nz[j,2]*a2[i,j]  (column broadcast)
__global__ void combine_kernel(const float4* __restrict__ a0, const float4* __restrict__ a1,
                               const float4* __restrict__ a2) {
    size_t t = (size_t)blockIdx.x * blockDim.x + threadIdx.x;
    const size_t total = (size_t)NV * NV / 4;
    if (t >= total) return;
    int j4 = (int)(t % (NV / 4));
    const float4* n0 = (const float4*)g_nzT[0];
    const float4* n1 = (const float4*)g_nzT[1];
    const float4* n2 = (const float4*)g_nzT[2];
    float4 v0 = a0[t], v1 = a1[t], v2 = a2[t];
    float4 w0 = n0[j4], w1 = n1[j4], w2 = n2[j4];
    float4 r;
    r.x = fmaf(w0.x, v0.x, fmaf(w1.x, v1.x, w2.x * v2.x));
    r.y = fmaf(w0.y, v0.y, fmaf(w1.y, v1.y, w2.y * v2.y));
    r.z = fmaf(w0.z, v0.z, fmaf(w1.z, v1.z, w2.z * v2.z));
    r.w = fmaf(w0.w, v0.w, fmaf(w1.w, v1.w, w2.w * v2.w));
    ((float4*)g_adj)[t] = r;
}

// ---------------- generic fp32 tiled GEMM  C[M,Nc] = A[M,Kc] (@) B ----------------
// BM=128, BN=128, BK=16, 256 threads, 8x8 register tile via packed FFMA2 (8x4 u64).
#define EPI_NONE 0
#define EPI_BIAS 1
#define EPI_BIAS_RELU 2
#define EPI_RELU 3
#define EPI_MUL 4

template <int EPI, bool TRANSB>
__global__ __launch_bounds__(256) void gemm_kernel(
    const float* __restrict__ A, const float* __restrict__ B, float* __restrict__ C,
    int M, int Nc, int Kc, int lda, int ldb,
    const float* __restrict__ bias, const float* __restrict__ elem) {
    __shared__ float As[16][128];
    __shared__ float Bs[16][128];
    int tid = threadIdx.x;
    int bm = blockIdx.y * 128;
    int bn = blockIdx.x * 128;
    int tx = tid & 15;
    int ty = tid >> 4;
    u64 acc2[8][4] = {};

    int arow = tid >> 1;
    int akk = (tid & 1) * 8;

    for (int k0 = 0; k0 < Kc; k0 += 16) {
        // stage A (transposed into smem: As[kk][row])
        {
            const float* ap = A + (size_t)(bm + arow) * lda + k0 + akk;
            float4 p0 = *(const float4*)ap;
            float4 p1 = *(const float4*)(ap + 4);
            As[akk + 0][arow] = p0.x;
            As[akk + 1][arow] = p0.y;
            As[akk + 2][arow] = p0.z;
            As[akk + 3][arow] = p0.w;
            As[akk + 4][arow] = p1.x;
            As[akk + 5][arow] = p1.y;
            As[akk + 6][arow] = p1.z;
            As[akk + 7][arow] = p1.w;
        }
        if (!TRANSB) {
            int bkk = tid >> 4;
            int bcol = (tid & 15) * 8;
            const float* bp = B + (size_t)(k0 + bkk) * ldb + bn + bcol;
            float4 zz = make_float4(0.f, 0.f, 0.f, 0.f);
            float4 b0 = (bn + bcol < Nc) ? *(const float4*)bp : zz;
            float4 b1 = (bn + bcol + 4 < Nc) ? *(const float4*)(bp + 4) : zz;
            *(float4*)&Bs[bkk][bcol] = b0;
            *(float4*)&Bs[bkk][bcol + 4] = b1;
        } else {
            int bcol = tid >> 1;
            int bkk = (tid & 1) * 8;
            const float* bp = B + (size_t)(bn + bcol) * ldb + k0 + bkk;
            float4 p0 = *(const float4*)bp;
            float4 p1 = *(const float4*)(bp + 4);
            Bs[bkk + 0][bcol] = p0.x;
            Bs[bkk + 1][bcol] = p0.y;
            Bs[bkk + 2][bcol] = p0.z;
            Bs[bkk + 3][bcol] = p0.w;
            Bs[bkk + 4][bcol] = p1.x;
            Bs[bkk + 5][bcol] = p1.y;
            Bs[bkk + 6][bcol] = p1.z;
            Bs[bkk + 7][bcol] = p1.w;
        }
        __syncthreads();
#pragma unroll
        for (int kk = 0; kk < 16; kk++) {
            float a[8];
            *(float4*)&a[0] = *(float4*)&As[kk][ty * 8];
            *(float4*)&a[4] = *(float4*)&As[kk][ty * 8 + 4];
            // b pairs straight out of smem as 64-bit words (lo = even col)
            const u64* bq = (const u64*)&Bs[kk][tx * 8];
            u64 b2[4];
#pragma unroll
            for (int j = 0; j < 4; j++) b2[j] = bq[j];
            u64 ad[8];
#pragma unroll
            for (int i = 0; i < 8; i++) ad[i] = pack2(a[i], a[i]);
#pragma unroll
            for (int i = 0; i < 8; i++)
#pragma unroll
                for (int j = 0; j < 4; j++) fma2(acc2[i][j], ad[i], b2[j]);
        }
        __syncthreads();
    }

#pragma unroll
    for (int i = 0; i < 8; i++) {
        int row = bm + ty * 8 + i;
        size_t base = (size_t)row * Nc;
#pragma unroll
        for (int j = 0; j < 4; j++) {
            float2 vp = unpack2(acc2[i][j]);
#pragma unroll
            for (int s = 0; s < 2; s++) {
                int col = bn + tx * 8 + j * 2 + s;
                if (col < Nc) {
                    float v = (s == 0) ? vp.x : vp.y;
                    if (EPI == EPI_BIAS || EPI == EPI_BIAS_RELU) v += bias[col];
                    if (EPI == EPI_BIAS_RELU || EPI == EPI_RELU) v = fmaxf(v, 0.f);
                    if (EPI == EPI_MUL) v *= elem[base + col];
                    C[base + col] = v;
                }
            }
        }
    }
}

// ---------------- row softmax over 6144-wide rows (in place) ----------------
__global__ __launch_bounds__(256) void softmax_rows_kernel(float* __restrict__ buf) {
    int row = blockIdx.x;
    float* p = buf + (size_t)row * NV;
    int tid = threadIdx.x;
    int lane = tid & 31, wid = tid >> 5;
    __shared__ float red[8];
    __shared__ float red2[8];

    float v[24];
    float mx = -3.0e38f;
#pragma unroll
    for (int t = 0; t < 24; t++) {
        v[t] = p[t * 256 + tid];
        mx = fmaxf(mx, v[t]);
    }
#pragma unroll
    for (int off = 16; off > 0; off >>= 1) mx = fmaxf(mx, __shfl_xor_sync(0xffffffffu, mx, off));
    if (lane == 0) red[wid] = mx;
    __syncthreads();
    float rowmax = red[0];
#pragma unroll
    for (int w = 1; w < 8; w++) rowmax = fmaxf(rowmax, red[w]);

    float s = 0.f;
#pragma unroll
    for (int t = 0; t < 24; t++) {
        v[t] = __expf(v[t] - rowmax);
        s += v[t];
    }
#pragma unroll
    for (int off = 16; off > 0; off >>= 1) s += __shfl_xor_sync(0xffffffffu, s, off);
    if (lane == 0) red2[wid] = s;
    __syncthreads();
    float tot = 0.f;
#pragma unroll
    for (int w = 0; w < 8; w++) tot += red2[w];
    float inv = 1.0f / tot;
#pragma unroll
    for (int t = 0; t < 24; t++) p[t * 256 + tid] = v[t] * inv;
}

// ---------------- final stage: z = adj @ u + b_g2 (N=16, k-split) ----------------
__global__ void init_z_kernel(const float* __restrict__ bg2) {
    int idx = blockIdx.x * blockDim.x + threadIdx.x;
    if (idx < NV * NC) g_z[idx] = bg2[idx % NC];
}

__global__ __launch_bounds__(256) void gemm_n16_ksplit(const float* __restrict__ A, int lda,
                                                       const float* __restrict__ Bm,
                                                       float* __restrict__ C, int Kchunk) {
    __shared__ float As[64][128];
    __shared__ float Bs[64][16];
    int tid = threadIdx.x;
    int bm = blockIdx.x * 128;
    int k0base = blockIdx.y * Kchunk;
    int col = tid & 15;
    int rowg = tid >> 4;
    float acc[8] = {};

    int arow = tid >> 1;
    int ak0 = (tid & 1) * 32;
    int bk = tid >> 2;
    int bc4 = (tid & 3) * 4;

    for (int k0 = k0base; k0 < k0base + Kchunk; k0 += 64) {
        float4 bv = *(const float4*)(Bm + (size_t)(k0 + bk) * 16 + bc4);
        *(float4*)&Bs[bk][bc4] = bv;
        const float* ap = A + (size_t)(bm + arow) * lda + k0 + ak0;
#pragma unroll
        for (int c = 0; c < 8; c++) {
            float4 av = *(const float4*)(ap + 4 * c);
            As[ak0 + 4 * c + 0][arow] = av.x;
            As[ak0 + 4 * c + 1][arow] = av.y;
            As[ak0 + 4 * c + 2][arow] = av.z;
            As[ak0 + 4 * c + 3][arow] = av.w;
        }
        __syncthreads();
#pragma unroll 8
        for (int kk = 0; kk < 64; kk++) {
            float b = Bs[kk][col];
#pragma unroll
            for (int i = 0; i < 8; i++) acc[i] = fmaf(As[kk][rowg * 8 + i], b, acc[i]);
        }
        __syncthreads();
    }
#pragma unroll
    for (int i = 0; i < 8; i++)
        atomicAdd(&C[(size_t)(bm + rowg * 8 + i) * NC + col], acc[i]);
}

__global__ void softmax16_kernel(const float* __restrict__ z, float* __restrict__ out) {
    int i = blockIdx.x * blockDim.x + threadIdx.x;
    if (i >= NV) return;
    float v[NC];
    float mx = -3.0e38f;
#pragma unroll
    for (int c = 0; c < NC; c++) {
        v[c] = z[i * NC + c];
        mx = fmaxf(mx, v[c]);
    }
    float s = 0.f;
#pragma unroll
    for (int c = 0; c < NC; c++) {
        v[c] = __expf(v[c] - mx);
        s += v[c];
    }
    float inv = 1.0f / s;
#pragma unroll
    for (int c = 0; c < NC; c++) out[i * NC + c] = v[c] * inv;
}

// ---------------- host orchestration ----------------
extern "C" void kernel_launch(void* const* d_in, const int* in_sizes, int n_in,
                              void* d_out, int out_size) {
    const float* adj0 = (const float*)d_in[0];
    const float* adj1 = (const float*)d_in[1];
    const float* adj2 = (const float*)d_in[2];
    const float* x = (const float*)d_in[3];
    const float* W_at1 = (const float*)d_in[4];
    const float* b_at1 = (const float*)d_in[5];
    const float* W_at2 = (const float*)d_in[6];
    const float* b_at2 = (const float*)d_in[7];
    const float* W_at3 = (const float*)d_in[8];
    const float* b_at3 = (const float*)d_in[9];
    const float* W_agg = (const float*)d_in[10];
    const float* b_agg = (const float*)d_in[11];
    const float* W_g1 = (const float*)d_in[12];
    const float* b_g1 = (const float*)d_in[13];
    const float* W_g2 = (const float*)d_in[14];
    const float* b_g2 = (const float*)d_in[15];
    const float* W_q = (const float*)d_in[16];
    const float* b_q = (const float*)d_in[17];
    const float* W_k = (const float*)d_in[18];
    const float* b_k = (const float*)d_in[19];
    const float* W_v = (const float*)d_in[20];
    const float* b_v = (const float*)d_in[21];
    float* out = (float*)d_out;

    void* p;
    cudaGetSymbolAddress(&p, g_adj);   float* adjS = (float*)p;
    cudaGetSymbolAddress(&p, g_att);   float* attS = (float*)p;
    cudaGetSymbolAddress(&p, g_xw);    float* xwS = (float*)p;
    cudaGetSymbolAddress(&p, g_h);     float* hS = (float*)p;
    cudaGetSymbolAddress(&p, g_Q);     float* QS = (float*)p;
    cudaGetSymbolAddress(&p, g_K);     float* KS = (float*)p;
    cudaGetSymbolAddress(&p, g_V);     float* VS = (float*)p;
    cudaGetSymbolAddress(&p, g_X);     float* XS = (float*)p;
    cudaGetSymbolAddress(&p, g_u);     float* uS = (float*)p;
    cudaGetSymbolAddress(&p, g_z);     float* zS = (float*)p;

    // 1. gating
    init_z123_kernel<<<(NV * 15 + 255) / 256, 256>>>(b_at1, b_at2, b_at3);
    gates_kernel<<<dim3(24, 24, 3), 256>>>(adj0, adj1, adj2, W_at1, W_at2, W_at3);
    nz_kernel<<<(NV + 255) / 256, 256>>>(W_agg, b_agg, out);

    // 2. combined adjacency
    combine_kernel<<<(unsigned)((size_t)NV * NV / 4 / 256), 256>>>(
        (const float4*)adj0, (const float4*)adj1, (const float4*)adj2);

    // 3. xw = x @ W_g1
    gemm_kernel<EPI_NONE, false><<<dim3(2, 48), 256>>>(x, W_g1, xwS, NV, NH, NF, NF, NH,
                                                       nullptr, nullptr);
    // 4. h = relu(adj @ xw + b_g1)
    gemm_kernel<EPI_BIAS_RELU, false><<<dim3(2, 48), 256>>>(adjS, xwS, hS, NV, NH, NV, NV, NH,
                                                            b_g1, nullptr);
    // 5. Q, K, V
    gemm_kernel<EPI_BIAS, false><<<dim3(2, 48), 256>>>(hS, W_q, QS, NV, NH, NH, NH, NH, b_q, nullptr);
    gemm_kernel<EPI_BIAS, false><<<dim3(2, 48), 256>>>(hS, W_k, KS, NV, NH, NH, NH, NH, b_k, nullptr);
    gemm_kernel<EPI_BIAS, false><<<dim3(2, 48), 256>>>(hS, W_v, VS, NV, NH, NH, NH, NH, b_v, nullptr);

    // 6. A_tilde = adj * (Q @ K^T)
    gemm_kernel<EPI_MUL, true><<<dim3(48, 48), 256>>>(QS, KS, attS, NV, NV, NH, NH, NH,
                                                      nullptr, adjS);
    // 7. attention = softmax(A_tilde, axis=1)   (gcn_norm == identity to ~1e-7)
    softmax_rows_kernel<<<NV, 256>>>(attS);

    // 8. X_tilde = relu(attention @ V)
    gemm_kernel<EPI_RELU, false><<<dim3(2, 48), 256>>>(attS, VS, XS, NV, NH, NV, NV, NH,
                                                       nullptr, nullptr);
    // 9. u = X_tilde @ W_g2
    gemm_kernel<EPI_NONE, false><<<dim3(1, 48), 256>>>(XS, W_g2, uS, NV, NC, NH, NH, NC,
                                                       nullptr, nullptr);
    // 10. z = adj @ u + b_g2 (k-split, atomic accumulate)
    init_z_kernel<<<(NV * NC + 255) / 256, 256>>>(b_g2);
    gemm_n16_ksplit<<<dim3(48, 8), 256>>>(adjS, NV, uS, zS, NV / 8);

    // 11. out[:, :16] = softmax(z)
    softmax16_kernel<<<(NV + 255) / 256, 256>>>(zS, out);

    (void)in_sizes; (void)n_in; (void)out_size;
}

// round 10
// speedup vs baseline: 1.3798x; 1.2864x over previous
#include <cuda_runtime.h>
#include <cuda_bf16.h>
#include <math.h>
#include <stdint.h>

#define NV 6144
#define NF 512
#define NH 256
#define NC 16

typedef unsigned long long u64;

// ================= packed f32x2 helpers (scalar GEMMs) =================
__device__ __forceinline__ u64 pack2(float lo, float hi) {
    u64 r; asm("mov.b64 %0, {%1, %2};" : "=l"(r) : "f"(lo), "f"(hi)); return r;
}
__device__ __forceinline__ void fma2(u64& d, u64 a, u64 b) {
    asm("fma.rn.f32x2 %0, %1, %2, %0;" : "+l"(d) : "l"(a), "l"(b));
}
__device__ __forceinline__ float2 unpack2(u64 v) {
    float2 r; asm("mov.b64 {%0, %1}, %2;" : "=f"(r.x), "=f"(r.y) : "l"(v)); return r;
}

// bf16 3-way split: a == hi + mid + lo up to ~2^-27 relative
__device__ __forceinline__ void split3(float a, __nv_bfloat16& h, __nv_bfloat16& m,
                                       __nv_bfloat16& l) {
    h = __float2bfloat16(a);
    float r1 = a - __bfloat162float(h);
    m = __float2bfloat16(r1);
    float r2 = r1 - __bfloat162float(m);
    l = __float2bfloat16(r2);
}

// m16n8k16 bf16 MMA, fp32 accumulate (portable sm_80+ encoding)
__device__ __forceinline__ void mma_bf16(float* acc, const uint32_t* a, const uint32_t* b) {
    asm volatile(
        "mma.sync.aligned.m16n8k16.row.col.f32.bf16.bf16.f32 "
        "{%0,%1,%2,%3}, {%4,%5,%6,%7}, {%8,%9}, {%0,%1,%2,%3};\n"
        : "+f"(acc[0]), "+f"(acc[1]), "+f"(acc[2]), "+f"(acc[3])
        : "r"(a[0]), "r"(a[1]), "r"(a[2]), "r"(a[3]), "r"(b[0]), "r"(b[1]));
}

// ================= scratch (device globals) =================
__device__ float g_adj[(size_t)NV * NV];
__device__ float g_att[(size_t)NV * NV];   // A_tilde (pre-softmax)
__device__ float g_z123[NV * 15];
__device__ float g_nzT[3][NV];
__device__ float g_xw[NV * NH];
__device__ float g_h[NV * NH];
__device__ float g_Q[NV * NH];
__device__ float g_K[NV * NH];
__device__ float g_V[NV * NH];
__device__ float g_X[NV * NH];
__device__ float g_u[NV * NC];
__device__ float g_z[NV * NC];
// bf16 split triplets
__device__ __nv_bfloat16 g_adjh[(size_t)NV * NV], g_adjm[(size_t)NV * NV], g_adjl[(size_t)NV * NV];
__device__ __nv_bfloat16 g_atth[(size_t)NV * NV], g_attm[(size_t)NV * NV], g_attl[(size_t)NV * NV];
__device__ __nv_bfloat16 g_qh[NV * NH], g_qm[NV * NH], g_ql[NV * NH];
__device__ __nv_bfloat16 g_kh[NV * NH], g_km[NV * NH], g_kl[NV * NH];
__device__ __nv_bfloat16 g_xwTh[NH * NV], g_xwTm[NH * NV], g_xwTl[NH * NV];
__device__ __nv_bfloat16 g_vTh[NH * NV], g_vTm[NH * NV], g_vTl[NH * NV];

// ================= gating pass =================
__global__ void init_z123_kernel(const float* __restrict__ b1, const float* __restrict__ b2,
                                 const float* __restrict__ b3) {
    int idx = blockIdx.x * blockDim.x + threadIdx.x;
    if (idx < NV * 15) {
        int f = idx % 15;
        int m = f / 5;
        const float* b = (m == 0) ? b1 : (m == 1) ? b2 : b3;
        g_z123[idx] = b[f % 5];
    }
}

__global__ __launch_bounds__(256) void gates_kernel(
    const float* __restrict__ a0, const float* __restrict__ a1, const float* __restrict__ a2,
    const float* __restrict__ W1, const float* __restrict__ W2, const float* __restrict__ W3) {
    int m = blockIdx.z;
    const float* A = (m == 0) ? a0 : (m == 1) ? a1 : a2;
    const float* W = (m == 0) ? W1 : (m == 1) ? W2 : W3;
    int warp = threadIdx.x >> 5;
    int lane = threadIdx.x & 31;
    int jbase = blockIdx.y * 256;
    int row0 = blockIdx.x * 256 + warp * 32;

    float w[8][5];
#pragma unroll
    for (int k = 0; k < 8; k++) {
        int j = jbase + k * 32 + lane;
#pragma unroll
        for (int f = 0; f < 5; f++) w[k][f] = W[j * 5 + f];
    }
    for (int r = 0; r < 32; r++) {
        int i = row0 + r;
        const float* arow = A + (size_t)i * NV + jbase;
        float ac0 = 0.f, ac1 = 0.f, ac2 = 0.f, ac3 = 0.f, ac4 = 0.f;
#pragma unroll
        for (int k = 0; k < 8; k++) {
            float a = arow[k * 32 + lane];
            ac0 = fmaf(a, w[k][0], ac0);
            ac1 = fmaf(a, w[k][1], ac1);
            ac2 = fmaf(a, w[k][2], ac2);
            ac3 = fmaf(a, w[k][3], ac3);
            ac4 = fmaf(a, w[k][4], ac4);
        }
#pragma unroll
        for (int off = 16; off > 0; off >>= 1) {
            ac0 += __shfl_xor_sync(0xffffffffu, ac0, off);
            ac1 += __shfl_xor_sync(0xffffffffu, ac1, off);
            ac2 += __shfl_xor_sync(0xffffffffu, ac2, off);
            ac3 += __shfl_xor_sync(0xffffffffu, ac3, off);
            ac4 += __shfl_xor_sync(0xffffffffu, ac4, off);
        }
        if (lane == 0) {
            float* zp = &g_z123[i * 15 + m * 5];
            atomicAdd(zp + 0, ac0);
            atomicAdd(zp + 1, ac1);
            atomicAdd(zp + 2, ac2);
            atomicAdd(zp + 3, ac3);
            atomicAdd(zp + 4, ac4);
        }
    }
}

__global__ void nz_kernel(const float* __restrict__ Wagg, const float* __restrict__ bagg,
                          float* __restrict__ out) {
    int i = blockIdx.x * blockDim.x + threadIdx.x;
    if (i >= NV) return;
    float zi[15];
#pragma unroll
    for (int f = 0; f < 15; f++) zi[f] = g_z123[i * 15 + f];
    float z4[3];
#pragma unroll
    for (int c = 0; c < 3; c++) {
        float s = bagg[c];
#pragma unroll
        for (int f = 0; f < 15; f++) s = fmaf(zi[f], Wagg[f * 3 + c], s);
        z4[c] = s;
    }
    float mx = fmaxf(z4[0], fmaxf(z4[1], z4[2]));
    float e0 = __expf(z4[0] - mx);
    float e1 = __expf(z4[1] - mx);
    float e2 = __expf(z4[2] - mx);
    float inv = 1.0f / (e0 + e1 + e2);
    float p0 = e0 * inv, p1 = e1 * inv, p2 = e2 * inv;
    g_nzT[0][i] = p0;
    g_nzT[1][i] = p1;
    g_nzT[2][i] = p2;
    out[NV * NC + i * 3 + 0] = p0;
    out[NV * NC + i * 3 + 1] = p1;
    out[NV * NC + i * 3 + 2] = p2;
}

// combined adjacency + bf16 splits
__global__ void combine_kernel(const float4* __restrict__ a0, const float4* __restrict__ a1,
                               const float4* __restrict__ a2) {
    size_t t = (size_t)blockIdx.x * blockDim.x + threadIdx.x;
    const size_t total = (size_t)NV * NV / 4;
    if (t >= total) return;
    int j4 = (int)(t % (NV / 4));
    const float4* n0 = (const float4*)g_nzT[0];
    const float4* n1 = (const float4*)g_nzT[1];
    const float4* n2 = (const float4*)g_nzT[2];
    float4 v0 = a0[t], v1 = a1[t], v2 = a2[t];
    float4 w0 = n0[j4], w1 = n1[j4], w2 = n2[j4];
    float4 r;
    r.x = fmaf(w0.x, v0.x, fmaf(w1.x, v1.x, w2.x * v2.x));
    r.y = fmaf(w0.y, v0.y, fmaf(w1.y, v1.y, w2.y * v2.y));
    r.z = fmaf(w0.z, v0.z, fmaf(w1.z, v1.z, w2.z * v2.z));
    r.w = fmaf(w0.w, v0.w, fmaf(w1.w, v1.w, w2.w * v2.w));
    ((float4*)g_adj)[t] = r;
    __align__(8) __nv_bfloat16 hb[4], mb[4], lb[4];
    split3(r.x, hb[0], mb[0], lb[0]);
    split3(r.y, hb[1], mb[1], lb[1]);
    split3(r.z, hb[2], mb[2], lb[2]);
    split3(r.w, hb[3], mb[3], lb[3]);
    *(uint2*)(g_adjh + 4 * t) = *(uint2*)hb;
    *(uint2*)(g_adjm + 4 * t) = *(uint2*)mb;
    *(uint2*)(g_adjl + 4 * t) = *(uint2*)lb;
}

// elementwise fp32 -> bf16 triplet
__global__ void split_kernel(const float* __restrict__ s, __nv_bfloat16* __restrict__ h,
                             __nv_bfloat16* __restrict__ m, __nv_bfloat16* __restrict__ l,
                             int n) {
    int i = blockIdx.x * blockDim.x + threadIdx.x;
    if (i < n) split3(s[i], h[i], m[i], l[i]);
}

// [NV,NH] fp32 -> [NH,NV] bf16 triplet (transpose + split)
__global__ __launch_bounds__(256) void transpose_split_kernel(
    const float* __restrict__ src, __nv_bfloat16* __restrict__ dh,
    __nv_bfloat16* __restrict__ dm, __nv_bfloat16* __restrict__ dl) {
    __shared__ float t[32][33];
    int j0 = blockIdx.x * 32;   // NV dim
    int n0 = blockIdx.y * 32;   // NH dim
    int x = threadIdx.x & 31;
    int y = threadIdx.x >> 5;   // 0..7
    for (int yy = y; yy < 32; yy += 8)
        t[yy][x] = src[(size_t)(j0 + yy) * NH + n0 + x];
    __syncthreads();
    for (int yy = y; yy < 32; yy += 8) {
        float v = t[x][yy];   // = src[j0+x][n0+yy]
        size_t o = (size_t)(n0 + yy) * NV + j0 + x;
        __nv_bfloat16 h, m, l;
        split3(v, h, m, l);
        dh[o] = h; dm[o] = m; dl[o] = l;
    }
}

// ================= tensor-core (mma.sync bf16) split GEMM =================
// C[M, Nc] = A @ B^T; A: [M, Kc] split-triplets, B: [Nc, Kc] split-triplets.
// CTA tile 128x128, K-stage 64, 8 warps of 64x32. 6 split products:
// (Ah,Bh),(Ah,Bm),(Ah,Bl),(Am,Bh),(Am,Bm),(Al,Bh).
#define EPI_NONE 0
#define EPI_BIAS 1
#define EPI_BIAS_RELU 2
#define EPI_RELU 3
#define EPI_MUL 4
#define SA 72                    // smem row stride in bf16 (bank-rotating pad)
#define TILE_ELEMS (128 * SA)    // 9216 bf16 per split tile
#define HSMEM_BYTES (6 * TILE_ELEMS * 2)  // 110592 B

template <int EPI>
__global__ __launch_bounds__(256, 2) void hmma_kernel(
    const __nv_bfloat16* __restrict__ Ah, const __nv_bfloat16* __restrict__ Am,
    const __nv_bfloat16* __restrict__ Al,
    const __nv_bfloat16* __restrict__ Bh, const __nv_bfloat16* __restrict__ Bm,
    const __nv_bfloat16* __restrict__ Bl,
    float* __restrict__ C, int Nc, int Kc,
    const float* __restrict__ bias, const float* __restrict__ elem) {
    extern __shared__ __align__(16) char smem_raw[];
    __nv_bfloat16* As = (__nv_bfloat16*)smem_raw;        // [3][128][SA]
    __nv_bfloat16* Bs = As + 3 * TILE_ELEMS;             // [3][128][SA]

    const int tid = threadIdx.x;
    const int wid = tid >> 5;
    const int lane = tid & 31;
    const int wm = wid >> 2;          // 0..1  (m block of 64)
    const int wn = wid & 3;           // 0..3  (n block of 32)
    const int m0 = blockIdx.y * 128;
    const int n0 = blockIdx.x * 128;
    const int lg = lane >> 2;         // group id 0..7
    const int lt = (lane & 3) * 2;    // k-pair base

    const __nv_bfloat16* Asrc[3] = {Ah, Am, Al};
    const __nv_bfloat16* Bsrc[3] = {Bh, Bm, Bl};

    float acc[4][4][4] = {};          // [mt][nt][frag]

    const int nstage = Kc >> 6;
    for (int stage = 0; stage < nstage; stage++) {
        const int k0 = stage << 6;
        // ---- stage 6 tiles [128 x 64 bf16] into padded smem ----
#pragma unroll
        for (int it = 0; it < 4; it++) {
            int idx = it * 256 + tid;     // 0..1023
            int r = idx >> 3;             // row 0..127
            int c8 = idx & 7;             // 8-bf16 chunk
            size_t aoff = (size_t)(m0 + r) * Kc + k0 + c8 * 8;
            size_t boff = (size_t)(n0 + r) * Kc + k0 + c8 * 8;
            int soff = r * SA + c8 * 8;
#pragma unroll
            for (int t = 0; t < 3; t++) {
                *(uint4*)(As + t * TILE_ELEMS + soff) = *(const uint4*)(Asrc[t] + aoff);
                *(uint4*)(Bs + t * TILE_ELEMS + soff) = *(const uint4*)(Bsrc[t] + boff);
            }
        }
        __syncthreads();

#pragma unroll 1
        for (int k16 = 0; k16 < 4; k16++) {
            const int kb = k16 * 16 + lt;
            // B fragments for all 3 splits (stay resident)
            uint32_t bfr[3][4][2];
#pragma unroll
            for (int t = 0; t < 3; t++)
#pragma unroll
                for (int nt = 0; nt < 4; nt++) {
                    const __nv_bfloat16* bp =
                        Bs + t * TILE_ELEMS + (wn * 32 + nt * 8 + lg) * SA + kb;
                    bfr[t][nt][0] = *(const uint32_t*)bp;
                    bfr[t][nt][1] = *(const uint32_t*)(bp + 8);
                }
            // A split groups: g=0 -> B{h,m,l}; g=1 -> B{h,m}; g=2 -> B{h}
#pragma unroll
            for (int g = 0; g < 3; g++) {
                uint32_t afr[4][4];
#pragma unroll
                for (int mt = 0; mt < 4; mt++) {
                    const __nv_bfloat16* ap =
                        As + g * TILE_ELEMS + (wm * 64 + mt * 16 + lg) * SA + kb;
                    afr[mt][0] = *(const uint32_t*)ap;
                    afr[mt][1] = *(const uint32_t*)(ap + 8 * SA);
                    afr[mt][2] = *(const uint32_t*)(ap + 8);
                    afr[mt][3] = *(const uint32_t*)(ap + 8 * SA + 8);
                }
                const int nb = (g == 0) ? 3 : ((g == 1) ? 2 : 1);
#pragma unroll
                for (int b = 0; b < 3; b++) {
                    if (b < nb) {
#pragma unroll
                        for (int mt = 0; mt < 4; mt++)
#pragma unroll
                            for (int nt = 0; nt < 4; nt++)
                                mma_bf16(acc[mt][nt], afr[mt], bfr[b][nt]);
                    }
                }
            }
        }
        __syncthreads();
    }

    // ---- epilogue ----
#pragma unroll
    for (int mt = 0; mt < 4; mt++) {
#pragma unroll
        for (int nt = 0; nt < 4; nt++) {
            int c0 = n0 + wn * 32 + nt * 8 + lt;
#pragma unroll
            for (int half = 0; half < 2; half++) {
                int row = m0 + wm * 64 + mt * 16 + lg + half * 8;
                size_t base = (size_t)row * Nc + c0;
                float v0 = acc[mt][nt][half * 2 + 0];
                float v1 = acc[mt][nt][half * 2 + 1];
                if (EPI == EPI_BIAS || EPI == EPI_BIAS_RELU) {
                    v0 += bias[c0];
                    v1 += bias[c0 + 1];
                }
                if (EPI == EPI_BIAS_RELU || EPI == EPI_RELU) {
                    v0 = fmaxf(v0, 0.f);
                    v1 = fmaxf(v1, 0.f);
                }
                if (EPI == EPI_MUL) {
                    v0 *= elem[base];
                    v1 *= elem[base + 1];
                }
                *(float2*)(C + base) = make_float2(v0, v1);
            }
        }
    }
}

// ================= scalar FFMA2 GEMM (small GEMMs) =================
template <int EPI, bool TRANSB>
__global__ __launch_bounds__(256) void gemm_kernel(
    const float* __restrict__ A, const float* __restrict__ B, float* __restrict__ C,
    int M, int Nc, int Kc, int lda, int ldb,
    const float* __restrict__ bias, const float* __restrict__ elem) {
    __shared__ float As[16][128];
    __shared__ float Bs[16][128];
    int tid = threadIdx.x;
    int bm = blockIdx.y * 128;
    int bn = blockIdx.x * 128;
    int tx = tid & 15;
    int ty = tid >> 4;
    u64 acc2[8][4] = {};
    int arow = tid >> 1;
    int akk = (tid & 1) * 8;

    for (int k0 = 0; k0 < Kc; k0 += 16) {
        {
            const float* ap = A + (size_t)(bm + arow) * lda + k0 + akk;
            float4 p0 = *(const float4*)ap;
            float4 p1 = *(const float4*)(ap + 4);
            As[akk + 0][arow] = p0.x; As[akk + 1][arow] = p0.y;
            As[akk + 2][arow] = p0.z; As[akk + 3][arow] = p0.w;
            As[akk + 4][arow] = p1.x; As[akk + 5][arow] = p1.y;
            As[akk + 6][arow] = p1.z; As[akk + 7][arow] = p1.w;
        }
        if (!TRANSB) {
            int bkk = tid >> 4;
            int bcol = (tid & 15) * 8;
            const float* bp = B + (size_t)(k0 + bkk) * ldb + bn + bcol;
            float4 zz = make_float4(0.f, 0.f, 0.f, 0.f);
            float4 b0 = (bn + bcol < Nc) ? *(const float4*)bp : zz;
            float4 b1 = (bn + bcol + 4 < Nc) ? *(const float4*)(bp + 4) : zz;
            *(float4*)&Bs[bkk][bcol] = b0;
            *(float4*)&Bs[bkk][bcol + 4] = b1;
        } else {
            int bcol = tid >> 1;
            int bkk = (tid & 1) * 8;
            const float* bp = B + (size_t)(bn + bcol) * ldb + k0 + bkk;
            float4 p0 = *(const float4*)bp;
            float4 p1 = *(const float4*)(bp + 4);
            Bs[bkk + 0][bcol] = p0.x; Bs[bkk + 1][bcol] = p0.y;
            Bs[bkk + 2][bcol] = p0.z; Bs[bkk + 3][bcol] = p0.w;
            Bs[bkk + 4][bcol] = p1.x; Bs[bkk + 5][bcol] = p1.y;
            Bs[bkk + 6][bcol] = p1.z; Bs[bkk + 7][bcol] = p1.w;
        }
        __syncthreads();
#pragma unroll
        for (int kk = 0; kk < 16; kk++) {
            float a[8];
            *(float4*)&a[0] = *(float4*)&As[kk][ty * 8];
            *(float4*)&a[4] = *(float4*)&As[kk][ty * 8 + 4];
            const u64* bq = (const u64*)&Bs[kk][tx * 8];
            u64 b2[4];
#pragma unroll
            for (int j = 0; j < 4; j++) b2[j] = bq[j];
            u64 ad[8];
#pragma unroll
            for (int i = 0; i < 8; i++) ad[i] = pack2(a[i], a[i]);
#pragma unroll
            for (int i = 0; i < 8; i++)
#pragma unroll
                for (int j = 0; j < 4; j++) fma2(acc2[i][j], ad[i], b2[j]);
        }
        __syncthreads();
    }
#pragma unroll
    for (int i = 0; i < 8; i++) {
        int row = bm + ty * 8 + i;
        size_t base = (size_t)row * Nc;
#pragma unroll
        for (int j = 0; j < 4; j++) {
            float2 vp = unpack2(acc2[i][j]);
#pragma unroll
            for (int s = 0; s < 2; s++) {
                int col = bn + tx * 8 + j * 2 + s;
                if (col < Nc) {
                    float v = (s == 0) ? vp.x : vp.y;
                    if (EPI == EPI_BIAS || EPI == EPI_BIAS_RELU) v += bias[col];
                    if (EPI == EPI_BIAS_RELU || EPI == EPI_RELU) v = fmaxf(v, 0.f);
                    if (EPI == EPI_MUL) v *= elem[base + col];
                    C[base + col] = v;
                }
            }
        }
    }
}

// ================= row softmax + att split output =================
__global__ __launch_bounds__(256) void softmax_rows_kernel(const float* __restrict__ buf) {
    int row = blockIdx.x;
    const float* p = buf + (size_t)row * NV;
    int tid = threadIdx.x;
    int lane = tid & 31, wid = tid >> 5;
    __shared__ float red[8];
    __shared__ float red2[8];

    float v[24];
    float mx = -3.0e38f;
#pragma unroll
    for (int t = 0; t < 24; t++) {
        v[t] = p[t * 256 + tid];
        mx = fmaxf(mx, v[t]);
    }
#pragma unroll
    for (int off = 16; off > 0; off >>= 1) mx = fmaxf(mx, __shfl_xor_sync(0xffffffffu, mx, off));
    if (lane == 0) red[wid] = mx;
    __syncthreads();
    float rowmax = red[0];
#pragma unroll
    for (int w = 1; w < 8; w++) rowmax = fmaxf(rowmax, red[w]);

    float s = 0.f;
#pragma unroll
    for (int t = 0; t < 24; t++) {
        v[t] = __expf(v[t] - rowmax);
        s += v[t];
    }
#pragma unroll
    for (int off = 16; off > 0; off >>= 1) s += __shfl_xor_sync(0xffffffffu, s, off);
    if (lane == 0) red2[wid] = s;
    __syncthreads();
    float tot = 0.f;
#pragma unroll
    for (int w = 0; w < 8; w++) tot += red2[w];
    float inv = 1.0f / tot;
#pragma unroll
    for (int t = 0; t < 24; t++) {
        float val = v[t] * inv;
        size_t o = (size_t)row * NV + t * 256 + tid;
        __nv_bfloat16 h, m, l;
        split3(val, h, m, l);
        g_atth[o] = h;
        g_attm[o] = m;
        g_attl[o] = l;
    }
}

// ================= final stage =================
__global__ void init_z_kernel(const float* __restrict__ bg2) {
    int idx = blockIdx.x * blockDim.x + threadIdx.x;
    if (idx < NV * NC) g_z[idx] = bg2[idx % NC];
}

__global__ __launch_bounds__(256) void gemm_n16_ksplit(const float* __restrict__ A, int lda,
                                                       const float* __restrict__ Bm,
                                                       float* __restrict__ C, int Kchunk) {
    __shared__ float As[64][128];
    __shared__ float Bs[64][16];
    int tid = threadIdx.x;
    int bm = blockIdx.x * 128;
    int k0base = blockIdx.y * Kchunk;
    int col = tid & 15;
    int rowg = tid >> 4;
    float acc[8] = {};
    int arow = tid >> 1;
    int ak0 = (tid & 1) * 32;
    int bk = tid >> 2;
    int bc4 = (tid & 3) * 4;

    for (int k0 = k0base; k0 < k0base + Kchunk; k0 += 64) {
        float4 bv = *(const float4*)(Bm + (size_t)(k0 + bk) * 16 + bc4);
        *(float4*)&Bs[bk][bc4] = bv;
        const float* ap = A + (size_t)(bm + arow) * lda + k0 + ak0;
#pragma unroll
        for (int c = 0; c < 8; c++) {
            float4 av = *(const float4*)(ap + 4 * c);
            As[ak0 + 4 * c + 0][arow] = av.x;
            As[ak0 + 4 * c + 1][arow] = av.y;
            As[ak0 + 4 * c + 2][arow] = av.z;
            As[ak0 + 4 * c + 3][arow] = av.w;
        }
        __syncthreads();
#pragma unroll 8
        for (int kk = 0; kk < 64; kk++) {
            float b = Bs[kk][col];
#pragma unroll
            for (int i = 0; i < 8; i++) acc[i] = fmaf(As[kk][rowg * 8 + i], b, acc[i]);
        }
        __syncthreads();
    }
#pragma unroll
    for (int i = 0; i < 8; i++)
        atomicAdd(&C[(size_t)(bm + rowg * 8 + i) * NC + col], acc[i]);
}

__global__ void softmax16_kernel(const float* __restrict__ z, float* __restrict__ out) {
    int i = blockIdx.x * blockDim.x + threadIdx.x;
    if (i >= NV) return;
    float v[NC];
    float mx = -3.0e38f;
#pragma unroll
    for (int c = 0; c < NC; c++) {
        v[c] = z[i * NC + c];
        mx = fmaxf(mx, v[c]);
    }
    float s = 0.f;
#pragma unroll
    for (int c = 0; c < NC; c++) {
        v[c] = __expf(v[c] - mx);
        s += v[c];
    }
    float inv = 1.0f / s;
#pragma unroll
    for (int c = 0; c < NC; c++) out[i * NC + c] = v[c] * inv;
}

// ================= host orchestration =================
static void* sym(const void* s) { void* p; cudaGetSymbolAddress(&p, s); return p; }

extern "C" void kernel_launch(void* const* d_in, const int* in_sizes, int n_in,
                              void* d_out, int out_size) {
    const float* adj0 = (const float*)d_in[0];
    const float* adj1 = (const float*)d_in[1];
    const float* adj2 = (const float*)d_in[2];
    const float* x = (const float*)d_in[3];
    const float* W_at1 = (const float*)d_in[4];
    const float* b_at1 = (const float*)d_in[5];
    const float* W_at2 = (const float*)d_in[6];
    const float* b_at2 = (const float*)d_in[7];
    const float* W_at3 = (const float*)d_in[8];
    const float* b_at3 = (const float*)d_in[9];
    const float* W_agg = (const float*)d_in[10];
    const float* b_agg = (const float*)d_in[11];
    const float* W_g1 = (const float*)d_in[12];
    const float* b_g1 = (const float*)d_in[13];
    const float* W_g2 = (const float*)d_in[14];
    const float* b_g2 = (const float*)d_in[15];
    const float* W_q = (const float*)d_in[16];
    const float* b_q = (const float*)d_in[17];
    const float* W_k = (const float*)d_in[18];
    const float* b_k = (const float*)d_in[19];
    const float* W_v = (const float*)d_in[20];
    const float* b_v = (const float*)d_in[21];
    float* out = (float*)d_out;

    float* adjS = (float*)sym(g_adj);
    float* attS = (float*)sym(g_att);
    float* xwS = (float*)sym(g_xw);
    float* hS = (float*)sym(g_h);
    float* QS = (float*)sym(g_Q);
    float* KS = (float*)sym(g_K);
    float* VS = (float*)sym(g_V);
    float* XS = (float*)sym(g_X);
    float* uS = (float*)sym(g_u);
    float* zS = (float*)sym(g_z);
    __nv_bfloat16* adjh = (__nv_bfloat16*)sym(g_adjh);
    __nv_bfloat16* adjm = (__nv_bfloat16*)sym(g_adjm);
    __nv_bfloat16* adjl = (__nv_bfloat16*)sym(g_adjl);
    __nv_bfloat16* atth = (__nv_bfloat16*)sym(g_atth);
    __nv_bfloat16* attm = (__nv_bfloat16*)sym(g_attm);
    __nv_bfloat16* attl = (__nv_bfloat16*)sym(g_attl);
    __nv_bfloat16* qh = (__nv_bfloat16*)sym(g_qh);
    __nv_bfloat16* qm = (__nv_bfloat16*)sym(g_qm);
    __nv_bfloat16* ql = (__nv_bfloat16*)sym(g_ql);
    __nv_bfloat16* kh = (__nv_bfloat16*)sym(g_kh);
    __nv_bfloat16* km = (__nv_bfloat16*)sym(g_km);
    __nv_bfloat16* kl = (__nv_bfloat16*)sym(g_kl);
    __nv_bfloat16* xwTh = (__nv_bfloat16*)sym(g_xwTh);
    __nv_bfloat16* xwTm = (__nv_bfloat16*)sym(g_xwTm);
    __nv_bfloat16* xwTl = (__nv_bfloat16*)sym(g_xwTl);
    __nv_bfloat16* vTh = (__nv_bfloat16*)sym(g_vTh);
    __nv_bfloat16* vTm = (__nv_bfloat16*)sym(g_vTm);
    __nv_bfloat16* vTl = (__nv_bfloat16*)sym(g_vTl);

    cudaFuncSetAttribute(hmma_kernel<EPI_BIAS_RELU>,
                         cudaFuncAttributeMaxDynamicSharedMemorySize, HSMEM_BYTES);
    cudaFuncSetAttribute(hmma_kernel<EPI_RELU>,
                         cudaFuncAttributeMaxDynamicSharedMemorySize, HSMEM_BYTES);
    cudaFuncSetAttribute(hmma_kernel<EPI_MUL>,
                         cudaFuncAttributeMaxDynamicSharedMemorySize, HSMEM_BYTES);

    // 1. gating
    init_z123_kernel<<<(NV * 15 + 255) / 256, 256>>>(b_at1, b_at2, b_at3);
    gates_kernel<<<dim3(24, 24, 3), 256>>>(adj0, adj1, adj2, W_at1, W_at2, W_at3);
    nz_kernel<<<(NV + 255) / 256, 256>>>(W_agg, b_agg, out);

    // 2. combined adjacency (fp32 + bf16 triplet)
    combine_kernel<<<(unsigned)((size_t)NV * NV / 4 / 256), 256>>>(
        (const float4*)adj0, (const float4*)adj1, (const float4*)adj2);

    // 3. xw = x @ W_g1 (scalar), then transpose-split
    gemm_kernel<EPI_NONE, false><<<dim3(2, 48), 256>>>(x, W_g1, xwS, NV, NH, NF, NF, NH,
                                                       nullptr, nullptr);
    transpose_split_kernel<<<dim3(NV / 32, NH / 32), 256>>>(xwS, xwTh, xwTm, xwTl);

    // 4. h = relu(adj @ xw + b_g1)  [tensor]
    hmma_kernel<EPI_BIAS_RELU><<<dim3(2, 48), 256, HSMEM_BYTES>>>(
        adjh, adjm, adjl, xwTh, xwTm, xwTl, hS, NH, NV, b_g1, nullptr);

    // 5. Q, K, V (scalar) + splits
    gemm_kernel<EPI_BIAS, false><<<dim3(2, 48), 256>>>(hS, W_q, QS, NV, NH, NH, NH, NH, b_q, nullptr);
    gemm_kernel<EPI_BIAS, false><<<dim3(2, 48), 256>>>(hS, W_k, KS, NV, NH, NH, NH, NH, b_k, nullptr);
    gemm_kernel<EPI_BIAS, false><<<dim3(2, 48), 256>>>(hS, W_v, VS, NV, NH, NH, NH, NH, b_v, nullptr);
    split_kernel<<<(NV * NH + 255) / 256, 256>>>(QS, qh, qm, ql, NV * NH);
    split_kernel<<<(NV * NH + 255) / 256, 256>>>(KS, kh, km, kl, NV * NH);
    transpose_split_kernel<<<dim3(NV / 32, NH / 32), 256>>>(VS, vTh, vTm, vTl);

    // 6. A_tilde = adj * (Q @ K^T)  [tensor]
    hmma_kernel<EPI_MUL><<<dim3(48, 48), 256, HSMEM_BYTES>>>(
        qh, qm, ql, kh, km, kl, attS, NV, NH, nullptr, adjS);

    // 7. attention = softmax(A_tilde) -> bf16 triplet (gcn_norm == identity to ~1e-7)
    softmax_rows_kernel<<<NV, 256>>>(attS);

    // 8. X_tilde = relu(attention @ V)  [tensor]
    hmma_kernel<EPI_RELU><<<dim3(2, 48), 256, HSMEM_BYTES>>>(
        atth, attm, attl, vTh, vTm, vTl, XS, NH, NV, nullptr, nullptr);

    // 9. u = X_tilde @ W_g2 (scalar)
    gemm_kernel<EPI_NONE, false><<<dim3(1, 48), 256>>>(XS, W_g2, uS, NV, NC, NH, NH, NC,
                                                       nullptr, nullptr);
    // 10. z = adj @ u + b_g2 (k-split scalar)
    init_z_kernel<<<(NV * NC + 255) / 256, 256>>>(b_g2);
    gemm_n16_ksplit<<<dim3(48, 8), 256>>>(adjS, NV, uS, zS, NV / 8);

    // 11. out[:, :16] = softmax(z)
    softmax16_kernel<<<(NV + 255) / 256, 256>>>(zS, out);

    (void)in_sizes; (void)n_in; (void)out_size;
}

// round 11
// speedup vs baseline: 1.5727x; 1.1398x over previous
#include <cuda_runtime.h>
#include <cuda_bf16.h>
#include <math.h>
#include <stdint.h>

#define NV 6144
#define NF 512
#define NH 256
#define NC 16

typedef unsigned long long u64;

// ================= packed f32x2 helpers (scalar GEMMs) =================
__device__ __forceinline__ u64 pack2(float lo, float hi) {
    u64 r; asm("mov.b64 %0, {%1, %2};" : "=l"(r) : "f"(lo), "f"(hi)); return r;
}
__device__ __forceinline__ void fma2(u64& d, u64 a, u64 b) {
    asm("fma.rn.f32x2 %0, %1, %2, %0;" : "+l"(d) : "l"(a), "l"(b));
}
__device__ __forceinline__ float2 unpack2(u64 v) {
    float2 r; asm("mov.b64 {%0, %1}, %2;" : "=f"(r.x), "=f"(r.y) : "l"(v)); return r;
}

// bf16 3-way split: a == hi + mid + lo up to ~2^-27 relative
__device__ __forceinline__ void split3(float a, __nv_bfloat16& h, __nv_bfloat16& m,
                                       __nv_bfloat16& l) {
    h = __float2bfloat16(a);
    float r1 = a - __bfloat162float(h);
    m = __float2bfloat16(r1);
    float r2 = r1 - __bfloat162float(m);
    l = __float2bfloat16(r2);
}

// m16n8k16 bf16 MMA, fp32 accumulate (portable sm_80+ encoding)
__device__ __forceinline__ void mma_bf16(float* acc, const uint32_t* a, const uint32_t* b) {
    asm volatile(
        "mma.sync.aligned.m16n8k16.row.col.f32.bf16.bf16.f32 "
        "{%0,%1,%2,%3}, {%4,%5,%6,%7}, {%8,%9}, {%0,%1,%2,%3};\n"
        : "+f"(acc[0]), "+f"(acc[1]), "+f"(acc[2]), "+f"(acc[3])
        : "r"(a[0]), "r"(a[1]), "r"(a[2]), "r"(a[3]), "r"(b[0]), "r"(b[1]));
}

__device__ __forceinline__ u64 to_global(const void* p) {
    u64 g; asm("cvta.to.global.u64 %0, %1;" : "=l"(g) : "l"(p)); return g;
}
#define CP16(dst_u32, src_g) \
    asm volatile("cp.async.cg.shared.global [%0], [%1], 16;" \
                 :: "r"(dst_u32), "l"(src_g) : "memory")

// ================= scratch (device globals) =================
__device__ float g_adj[(size_t)NV * NV];
__device__ float g_att[(size_t)NV * NV];   // A_tilde (pre-softmax)
__device__ float g_z123[NV * 15];
__device__ float g_nzT[3][NV];
__device__ float g_xw[NV * NH];
__device__ float g_h[NV * NH];
__device__ float g_Q[NV * NH];
__device__ float g_K[NV * NH];
__device__ float g_V[NV * NH];
__device__ float g_X[NV * NH];
__device__ float g_u[NV * NC];
__device__ float g_z[NV * NC];
// bf16 split triplets
__device__ __nv_bfloat16 g_adjh[(size_t)NV * NV], g_adjm[(size_t)NV * NV], g_adjl[(size_t)NV * NV];
__device__ __nv_bfloat16 g_atth[(size_t)NV * NV], g_attm[(size_t)NV * NV], g_attl[(size_t)NV * NV];
__device__ __nv_bfloat16 g_qh[NV * NH], g_qm[NV * NH], g_ql[NV * NH];
__device__ __nv_bfloat16 g_kh[NV * NH], g_km[NV * NH], g_kl[NV * NH];
__device__ __nv_bfloat16 g_xwTh[NH * NV], g_xwTm[NH * NV], g_xwTl[NH * NV];
__device__ __nv_bfloat16 g_vTh[NH * NV], g_vTm[NH * NV], g_vTl[NH * NV];

// ================= gating pass =================
__global__ void init_z123_kernel(const float* __restrict__ b1, const float* __restrict__ b2,
                                 const float* __restrict__ b3) {
    int idx = blockIdx.x * blockDim.x + threadIdx.x;
    if (idx < NV * 15) {
        int f = idx % 15;
        int m = f / 5;
        const float* b = (m == 0) ? b1 : (m == 1) ? b2 : b3;
        g_z123[idx] = b[f % 5];
    }
}

__global__ __launch_bounds__(256) void gates_kernel(
    const float* __restrict__ a0, const float* __restrict__ a1, const float* __restrict__ a2,
    const float* __restrict__ W1, const float* __restrict__ W2, const float* __restrict__ W3) {
    int m = blockIdx.z;
    const float* A = (m == 0) ? a0 : (m == 1) ? a1 : a2;
    const float* W = (m == 0) ? W1 : (m == 1) ? W2 : W3;
    int warp = threadIdx.x >> 5;
    int lane = threadIdx.x & 31;
    int jbase = blockIdx.y * 256;
    int row0 = blockIdx.x * 256 + warp * 32;

    float w[8][5];
#pragma unroll
    for (int k = 0; k < 8; k++) {
        int j = jbase + k * 32 + lane;
#pragma unroll
        for (int f = 0; f < 5; f++) w[k][f] = W[j * 5 + f];
    }
    for (int r = 0; r < 32; r++) {
        int i = row0 + r;
        const float* arow = A + (size_t)i * NV + jbase;
        float ac0 = 0.f, ac1 = 0.f, ac2 = 0.f, ac3 = 0.f, ac4 = 0.f;
#pragma unroll
        for (int k = 0; k < 8; k++) {
            float a = arow[k * 32 + lane];
            ac0 = fmaf(a, w[k][0], ac0);
            ac1 = fmaf(a, w[k][1], ac1);
            ac2 = fmaf(a, w[k][2], ac2);
            ac3 = fmaf(a, w[k][3], ac3);
            ac4 = fmaf(a, w[k][4], ac4);
        }
#pragma unroll
        for (int off = 16; off > 0; off >>= 1) {
            ac0 += __shfl_xor_sync(0xffffffffu, ac0, off);
            ac1 += __shfl_xor_sync(0xffffffffu, ac1, off);
            ac2 += __shfl_xor_sync(0xffffffffu, ac2, off);
            ac3 += __shfl_xor_sync(0xffffffffu, ac3, off);
            ac4 += __shfl_xor_sync(0xffffffffu, ac4, off);
        }
        if (lane == 0) {
            float* zp = &g_z123[i * 15 + m * 5];
            atomicAdd(zp + 0, ac0);
            atomicAdd(zp + 1, ac1);
            atomicAdd(zp + 2, ac2);
            atomicAdd(zp + 3, ac3);
            atomicAdd(zp + 4, ac4);
        }
    }
}

__global__ void nz_kernel(const float* __restrict__ Wagg, const float* __restrict__ bagg,
                          float* __restrict__ out) {
    int i = blockIdx.x * blockDim.x + threadIdx.x;
    if (i >= NV) return;
    float zi[15];
#pragma unroll
    for (int f = 0; f < 15; f++) zi[f] = g_z123[i * 15 + f];
    float z4[3];
#pragma unroll
    for (int c = 0; c < 3; c++) {
        float s = bagg[c];
#pragma unroll
        for (int f = 0; f < 15; f++) s = fmaf(zi[f], Wagg[f * 3 + c], s);
        z4[c] = s;
    }
    float mx = fmaxf(z4[0], fmaxf(z4[1], z4[2]));
    float e0 = __expf(z4[0] - mx);
    float e1 = __expf(z4[1] - mx);
    float e2 = __expf(z4[2] - mx);
    float inv = 1.0f / (e0 + e1 + e2);
    float p0 = e0 * inv, p1 = e1 * inv, p2 = e2 * inv;
    g_nzT[0][i] = p0;
    g_nzT[1][i] = p1;
    g_nzT[2][i] = p2;
    out[NV * NC + i * 3 + 0] = p0;
    out[NV * NC + i * 3 + 1] = p1;
    out[NV * NC + i * 3 + 2] = p2;
}

// combined adjacency + bf16 splits
__global__ void combine_kernel(const float4* __restrict__ a0, const float4* __restrict__ a1,
                               const float4* __restrict__ a2) {
    size_t t = (size_t)blockIdx.x * blockDim.x + threadIdx.x;
    const size_t total = (size_t)NV * NV / 4;
    if (t >= total) return;
    int j4 = (int)(t % (NV / 4));
    const float4* n0 = (const float4*)g_nzT[0];
    const float4* n1 = (const float4*)g_nzT[1];
    const float4* n2 = (const float4*)g_nzT[2];
    float4 v0 = a0[t], v1 = a1[t], v2 = a2[t];
    float4 w0 = n0[j4], w1 = n1[j4], w2 = n2[j4];
    float4 r;
    r.x = fmaf(w0.x, v0.x, fmaf(w1.x, v1.x, w2.x * v2.x));
    r.y = fmaf(w0.y, v0.y, fmaf(w1.y, v1.y, w2.y * v2.y));
    r.z = fmaf(w0.z, v0.z, fmaf(w1.z, v1.z, w2.z * v2.z));
    r.w = fmaf(w0.w, v0.w, fmaf(w1.w, v1.w, w2.w * v2.w));
    ((float4*)g_adj)[t] = r;
    __align__(8) __nv_bfloat16 hb[4], mb[4], lb[4];
    split3(r.x, hb[0], mb[0], lb[0]);
    split3(r.y, hb[1], mb[1], lb[1]);
    split3(r.z, hb[2], mb[2], lb[2]);
    split3(r.w, hb[3], mb[3], lb[3]);
    *(uint2*)(g_adjh + 4 * t) = *(uint2*)hb;
    *(uint2*)(g_adjm + 4 * t) = *(uint2*)mb;
    *(uint2*)(g_adjl + 4 * t) = *(uint2*)lb;
}

// elementwise fp32 -> bf16 triplet
__global__ void split_kernel(const float* __restrict__ s, __nv_bfloat16* __restrict__ h,
                             __nv_bfloat16* __restrict__ m, __nv_bfloat16* __restrict__ l,
                             int n) {
    int i = blockIdx.x * blockDim.x + threadIdx.x;
    if (i < n) split3(s[i], h[i], m[i], l[i]);
}

// [NV,NH] fp32 -> [NH,NV] bf16 triplet (transpose + split)
__global__ __launch_bounds__(256) void transpose_split_kernel(
    const float* __restrict__ src, __nv_bfloat16* __restrict__ dh,
    __nv_bfloat16* __restrict__ dm, __nv_bfloat16* __restrict__ dl) {
    __shared__ float t[32][33];
    int j0 = blockIdx.x * 32;   // NV dim
    int n0 = blockIdx.y * 32;   // NH dim
    int x = threadIdx.x & 31;
    int y = threadIdx.x >> 5;   // 0..7
    for (int yy = y; yy < 32; yy += 8)
        t[yy][x] = src[(size_t)(j0 + yy) * NH + n0 + x];
    __syncthreads();
    for (int yy = y; yy < 32; yy += 8) {
        float v = t[x][yy];   // = src[j0+x][n0+yy]
        size_t o = (size_t)(n0 + yy) * NV + j0 + x;
        __nv_bfloat16 h, m, l;
        split3(v, h, m, l);
        dh[o] = h; dm[o] = m; dl[o] = l;
    }
}

// ================= tensor-core (mma.sync bf16) split GEMM =================
// C[M, Nc] = A @ B^T; A: [M, Kc] split-triplets, B: [Nc, Kc] split-triplets.
// CTA tile 128x128, K-stage 64, 16 warps of 32x32, double-buffered cp.async.
// 6 split products: (Ah,Bh),(Ah,Bm),(Ah,Bl),(Am,Bh),(Am,Bm),(Al,Bh).
#define EPI_NONE 0
#define EPI_BIAS 1
#define EPI_BIAS_RELU 2
#define EPI_RELU 3
#define EPI_MUL 4
#define SA 72                       // smem row stride in bf16 (bank-rotating pad)
#define TILE_ELEMS (128 * SA)       // 9216 bf16 per split tile
#define TILE_BYTES (TILE_ELEMS * 2) // 18432 B
#define BUF_BYTES (6 * TILE_BYTES)  // 110592 B per pipeline buffer
#define HSMEM_BYTES (2 * BUF_BYTES) // 221184 B (double buffered)

template <int EPI>
__global__ __launch_bounds__(512, 1) void hmma_kernel(
    const __nv_bfloat16* __restrict__ Ah, const __nv_bfloat16* __restrict__ Am,
    const __nv_bfloat16* __restrict__ Al,
    const __nv_bfloat16* __restrict__ Bh, const __nv_bfloat16* __restrict__ Bm,
    const __nv_bfloat16* __restrict__ Bl,
    float* __restrict__ C, int Nc, int Kc,
    const float* __restrict__ bias, const float* __restrict__ elem) {
    extern __shared__ __align__(16) char smem_raw[];
    const uint32_t smem_u32 = (uint32_t)__cvta_generic_to_shared(smem_raw);

    const int tid = threadIdx.x;
    const int wid = tid >> 5;
    const int lane = tid & 31;
    const int wm = wid >> 2;          // 0..3  (m block of 32)
    const int wn = wid & 3;           // 0..3  (n block of 32)
    const int m0 = blockIdx.y * 128;
    const int n0 = blockIdx.x * 128;
    const int lg = lane >> 2;         // group id 0..7
    const int lt = (lane & 3) * 2;    // k-pair base

    u64 ga[3], gb[3];
    ga[0] = to_global(Ah); ga[1] = to_global(Am); ga[2] = to_global(Al);
    gb[0] = to_global(Bh); gb[1] = to_global(Bm); gb[2] = to_global(Bl);

    float acc[2][4][4] = {};          // [mt][nt][frag]
    const int nstage = Kc >> 6;

    // ---- async stage issue: 6 tiles [128 x 64 bf16] into buffer `buf` ----
    auto issue_stage = [&](int stage, int buf) {
        const int k0 = stage << 6;
#pragma unroll
        for (int it = 0; it < 2; it++) {
            int idx = it * 512 + tid;     // 0..1023
            int r = idx >> 3;             // row 0..127
            int c8 = idx & 7;             // 8-bf16 chunk
            uint32_t soff = smem_u32 + buf * BUF_BYTES + (uint32_t)(r * SA + c8 * 8) * 2;
            u64 aoff = ((u64)(m0 + r) * Kc + k0 + c8 * 8) * 2;
            u64 boff = ((u64)(n0 + r) * Kc + k0 + c8 * 8) * 2;
#pragma unroll
            for (int t = 0; t < 3; t++) {
                CP16(soff + t * TILE_BYTES, ga[t] + aoff);
                CP16(soff + (3 + t) * TILE_BYTES, gb[t] + boff);
            }
        }
        asm volatile("cp.async.commit_group;" ::: "memory");
    };

    issue_stage(0, 0);

    for (int stage = 0; stage < nstage; stage++) {
        const int buf = stage & 1;
        if (stage + 1 < nstage) {
            issue_stage(stage + 1, (stage + 1) & 1);
            asm volatile("cp.async.wait_group 1;" ::: "memory");
        } else {
            asm volatile("cp.async.wait_group 0;" ::: "memory");
        }
        __syncthreads();

        const __nv_bfloat16* base = (const __nv_bfloat16*)smem_raw + buf * 6 * TILE_ELEMS;
        const __nv_bfloat16* As = base;
        const __nv_bfloat16* Bs = base + 3 * TILE_ELEMS;

#pragma unroll 1
        for (int k16 = 0; k16 < 4; k16++) {
            const int kb = k16 * 16 + lt;
            // B fragments for all 3 splits (resident)
            uint32_t bfr[3][4][2];
#pragma unroll
            for (int t = 0; t < 3; t++)
#pragma unroll
                for (int nt = 0; nt < 4; nt++) {
                    const __nv_bfloat16* bp =
                        Bs + t * TILE_ELEMS + (wn * 32 + nt * 8 + lg) * SA + kb;
                    bfr[t][nt][0] = *(const uint32_t*)bp;
                    bfr[t][nt][1] = *(const uint32_t*)(bp + 8);
                }
            // A split groups: g=0 -> B{h,m,l}; g=1 -> B{h,m}; g=2 -> B{h}
#pragma unroll
            for (int g = 0; g < 3; g++) {
                uint32_t afr[2][4];
#pragma unroll
                for (int mt = 0; mt < 2; mt++) {
                    const __nv_bfloat16* ap =
                        As + g * TILE_ELEMS + (wm * 32 + mt * 16 + lg) * SA + kb;
                    afr[mt][0] = *(const uint32_t*)ap;
                    afr[mt][1] = *(const uint32_t*)(ap + 8 * SA);
                    afr[mt][2] = *(const uint32_t*)(ap + 8);
                    afr[mt][3] = *(const uint32_t*)(ap + 8 * SA + 8);
                }
                const int nb = (g == 0) ? 3 : ((g == 1) ? 2 : 1);
#pragma unroll
                for (int b = 0; b < 3; b++) {
                    if (b < nb) {
#pragma unroll
                        for (int mt = 0; mt < 2; mt++)
#pragma unroll
                            for (int nt = 0; nt < 4; nt++)
                                mma_bf16(acc[mt][nt], afr[mt], bfr[b][nt]);
                    }
                }
            }
        }
        __syncthreads();
    }

    // ---- epilogue ----
#pragma unroll
    for (int mt = 0; mt < 2; mt++) {
#pragma unroll
        for (int nt = 0; nt < 4; nt++) {
            int c0 = n0 + wn * 32 + nt * 8 + lt;
#pragma unroll
            for (int half = 0; half < 2; half++) {
                int row = m0 + wm * 32 + mt * 16 + lg + half * 8;
                size_t base = (size_t)row * Nc + c0;
                float v0 = acc[mt][nt][half * 2 + 0];
                float v1 = acc[mt][nt][half * 2 + 1];
                if (EPI == EPI_BIAS || EPI == EPI_BIAS_RELU) {
                    v0 += bias[c0];
                    v1 += bias[c0 + 1];
                }
                if (EPI == EPI_BIAS_RELU || EPI == EPI_RELU) {
                    v0 = fmaxf(v0, 0.f);
                    v1 = fmaxf(v1, 0.f);
                }
                if (EPI == EPI_MUL) {
                    v0 *= elem[base];
                    v1 *= elem[base + 1];
                }
                *(float2*)(C + base) = make_float2(v0, v1);
            }
        }
    }
}

// ================= scalar FFMA2 GEMM (small GEMMs) =================
template <int EPI, bool TRANSB>
__global__ __launch_bounds__(256) void gemm_kernel(
    const float* __restrict__ A, const float* __restrict__ B, float* __restrict__ C,
    int M, int Nc, int Kc, int lda, int ldb,
    const float* __restrict__ bias, const float* __restrict__ elem) {
    __shared__ float As[16][128];
    __shared__ float Bs[16][128];
    int tid = threadIdx.x;
    int bm = blockIdx.y * 128;
    int bn = blockIdx.x * 128;
    int tx = tid & 15;
    int ty = tid >> 4;
    u64 acc2[8][4] = {};
    int arow = tid >> 1;
    int akk = (tid & 1) * 8;

    for (int k0 = 0; k0 < Kc; k0 += 16) {
        {
            const float* ap = A + (size_t)(bm + arow) * lda + k0 + akk;
            float4 p0 = *(const float4*)ap;
            float4 p1 = *(const float4*)(ap + 4);
            As[akk + 0][arow] = p0.x; As[akk + 1][arow] = p0.y;
            As[akk + 2][arow] = p0.z; As[akk + 3][arow] = p0.w;
            As[akk + 4][arow] = p1.x; As[akk + 5][arow] = p1.y;
            As[akk + 6][arow] = p1.z; As[akk + 7][arow] = p1.w;
        }
        if (!TRANSB) {
            int bkk = tid >> 4;
            int bcol = (tid & 15) * 8;
            const float* bp = B + (size_t)(k0 + bkk) * ldb + bn + bcol;
            float4 zz = make_float4(0.f, 0.f, 0.f, 0.f);
            float4 b0 = (bn + bcol < Nc) ? *(const float4*)bp : zz;
            float4 b1 = (bn + bcol + 4 < Nc) ? *(const float4*)(bp + 4) : zz;
            *(float4*)&Bs[bkk][bcol] = b0;
            *(float4*)&Bs[bkk][bcol + 4] = b1;
        } else {
            int bcol = tid >> 1;
            int bkk = (tid & 1) * 8;
            const float* bp = B + (size_t)(bn + bcol) * ldb + k0 + bkk;
            float4 p0 = *(const float4*)bp;
            float4 p1 = *(const float4*)(bp + 4);
            Bs[bkk + 0][bcol] = p0.x; Bs[bkk + 1][bcol] = p0.y;
            Bs[bkk + 2][bcol] = p0.z; Bs[bkk + 3][bcol] = p0.w;
            Bs[bkk + 4][bcol] = p1.x; Bs[bkk + 5][bcol] = p1.y;
            Bs[bkk + 6][bcol] = p1.z; Bs[bkk + 7][bcol] = p1.w;
        }
        __syncthreads();
#pragma unroll
        for (int kk = 0; kk < 16; kk++) {
            float a[8];
            *(float4*)&a[0] = *(float4*)&As[kk][ty * 8];
            *(float4*)&a[4] = *(float4*)&As[kk][ty * 8 + 4];
            const u64* bq = (const u64*)&Bs[kk][tx * 8];
            u64 b2[4];
#pragma unroll
            for (int j = 0; j < 4; j++) b2[j] = bq[j];
            u64 ad[8];
#pragma unroll
            for (int i = 0; i < 8; i++) ad[i] = pack2(a[i], a[i]);
#pragma unroll
            for (int i = 0; i < 8; i++)
#pragma unroll
                for (int j = 0; j < 4; j++) fma2(acc2[i][j], ad[i], b2[j]);
        }
        __syncthreads();
    }
#pragma unroll
    for (int i = 0; i < 8; i++) {
        int row = bm + ty * 8 + i;
        size_t base = (size_t)row * Nc;
#pragma unroll
        for (int j = 0; j < 4; j++) {
            float2 vp = unpack2(acc2[i][j]);
#pragma unroll
            for (int s = 0; s < 2; s++) {
                int col = bn + tx * 8 + j * 2 + s;
                if (col < Nc) {
                    float v = (s == 0) ? vp.x : vp.y;
                    if (EPI == EPI_BIAS || EPI == EPI_BIAS_RELU) v += bias[col];
                    if (EPI == EPI_BIAS_RELU || EPI == EPI_RELU) v = fmaxf(v, 0.f);
                    if (EPI == EPI_MUL) v *= elem[base + col];
                    C[base + col] = v;
                }
            }
        }
    }
}

// ================= row softmax + att split output =================
__global__ __launch_bounds__(256) void softmax_rows_kernel(const float* __restrict__ buf) {
    int row = blockIdx.x;
    const float* p = buf + (size_t)row * NV;
    int tid = threadIdx.x;
    int lane = tid & 31, wid = tid >> 5;
    __shared__ float red[8];
    __shared__ float red2[8];

    float v[24];
    float mx = -3.0e38f;
#pragma unroll
    for (int t = 0; t < 24; t++) {
        v[t] = p[t * 256 + tid];
        mx = fmaxf(mx, v[t]);
    }
#pragma unroll
    for (int off = 16; off > 0; off >>= 1) mx = fmaxf(mx, __shfl_xor_sync(0xffffffffu, mx, off));
    if (lane == 0) red[wid] = mx;
    __syncthreads();
    float rowmax = red[0];
#pragma unroll
    for (int w = 1; w < 8; w++) rowmax = fmaxf(rowmax, red[w]);

    float s = 0.f;
#pragma unroll
    for (int t = 0; t < 24; t++) {
        v[t] = __expf(v[t] - rowmax);
        s += v[t];
    }
#pragma unroll
    for (int off = 16; off > 0; off >>= 1) s += __shfl_xor_sync(0xffffffffu, s, off);
    if (lane == 0) red2[wid] = s;
    __syncthreads();
    float tot = 0.f;
#pragma unroll
    for (int w = 0; w < 8; w++) tot += red2[w];
    float inv = 1.0f / tot;
#pragma unroll
    for (int t = 0; t < 24; t++) {
        float val = v[t] * inv;
        size_t o = (size_t)row * NV + t * 256 + tid;
        __nv_bfloat16 h, m, l;
        split3(val, h, m, l);
        g_atth[o] = h;
        g_attm[o] = m;
        g_attl[o] = l;
    }
}

// ================= final stage =================
__global__ void init_z_kernel(const float* __restrict__ bg2) {
    int idx = blockIdx.x * blockDim.x + threadIdx.x;
    if (idx < NV * NC) g_z[idx] = bg2[idx % NC];
}

__global__ __launch_bounds__(256) void gemm_n16_ksplit(const float* __restrict__ A, int lda,
                                                       const float* __restrict__ Bm,
                                                       float* __restrict__ C, int Kchunk) {
    __shared__ float As[64][128];
    __shared__ float Bs[64][16];
    int tid = threadIdx.x;
    int bm = blockIdx.x * 128;
    int k0base = blockIdx.y * Kchunk;
    int col = tid & 15;
    int rowg = tid >> 4;
    float acc[8] = {};
    int arow = tid >> 1;
    int ak0 = (tid & 1) * 32;
    int bk = tid >> 2;
    int bc4 = (tid & 3) * 4;

    for (int k0 = k0base; k0 < k0base + Kchunk; k0 += 64) {
        float4 bv = *(const float4*)(Bm + (size_t)(k0 + bk) * 16 + bc4);
        *(float4*)&Bs[bk][bc4] = bv;
        const float* ap = A + (size_t)(bm + arow) * lda + k0 + ak0;
#pragma unroll
        for (int c = 0; c < 8; c++) {
            float4 av = *(const float4*)(ap + 4 * c);
            As[ak0 + 4 * c + 0][arow] = av.x;
            As[ak0 + 4 * c + 1][arow] = av.y;
            As[ak0 + 4 * c + 2][arow] = av.z;
            As[ak0 + 4 * c + 3][arow] = av.w;
        }
        __syncthreads();
#pragma unroll 8
        for (int kk = 0; kk < 64; kk++) {
            float b = Bs[kk][col];
#pragma unroll
            for (int i = 0; i < 8; i++) acc[i] = fmaf(As[kk][rowg * 8 + i], b, acc[i]);
        }
        __syncthreads();
    }
#pragma unroll
    for (int i = 0; i < 8; i++)
        atomicAdd(&C[(size_t)(bm + rowg * 8 + i) * NC + col], acc[i]);
}

__global__ void softmax16_kernel(const float* __restrict__ z, float* __restrict__ out) {
    int i = blockIdx.x * blockDim.x + threadIdx.x;
    if (i >= NV) return;
    float v[NC];
    float mx = -3.0e38f;
#pragma unroll
    for (int c = 0; c < NC; c++) {
        v[c] = z[i * NC + c];
        mx = fmaxf(mx, v[c]);
    }
    float s = 0.f;
#pragma unroll
    for (int c = 0; c < NC; c++) {
        v[c] = __expf(v[c] - mx);
        s += v[c];
    }
    float inv = 1.0f / s;
#pragma unroll
    for (int c = 0; c < NC; c++) out[i * NC + c] = v[c] * inv;
}

// ================= host orchestration =================
static void* sym(const void* s) { void* p; cudaGetSymbolAddress(&p, s); return p; }

extern "C" void kernel_launch(void* const* d_in, const int* in_sizes, int n_in,
                              void* d_out, int out_size) {
    const float* adj0 = (const float*)d_in[0];
    const float* adj1 = (const float*)d_in[1];
    const float* adj2 = (const float*)d_in[2];
    const float* x = (const float*)d_in[3];
    const float* W_at1 = (const float*)d_in[4];
    const float* b_at1 = (const float*)d_in[5];
    const float* W_at2 = (const float*)d_in[6];
    const float* b_at2 = (const float*)d_in[7];
    const float* W_at3 = (const float*)d_in[8];
    const float* b_at3 = (const float*)d_in[9];
    const float* W_agg = (const float*)d_in[10];
    const float* b_agg = (const float*)d_in[11];
    const float* W_g1 = (const float*)d_in[12];
    const float* b_g1 = (const float*)d_in[13];
    const float* W_g2 = (const float*)d_in[14];
    const float* b_g2 = (const float*)d_in[15];
    const float* W_q = (const float*)d_in[16];
    const float* b_q = (const float*)d_in[17];
    const float* W_k = (const float*)d_in[18];
    const float* b_k = (const float*)d_in[19];
    const float* W_v = (const float*)d_in[20];
    const float* b_v = (const float*)d_in[21];
    float* out = (float*)d_out;

    float* adjS = (float*)sym(g_adj);
    float* attS = (float*)sym(g_att);
    float* xwS = (float*)sym(g_xw);
    float* hS = (float*)sym(g_h);
    float* QS = (float*)sym(g_Q);
    float* KS = (float*)sym(g_K);
    float* VS = (float*)sym(g_V);
    float* XS = (float*)sym(g_X);
    float* uS = (float*)sym(g_u);
    float* zS = (float*)sym(g_z);
    __nv_bfloat16* adjh = (__nv_bfloat16*)sym(g_adjh);
    __nv_bfloat16* adjm = (__nv_bfloat16*)sym(g_adjm);
    __nv_bfloat16* adjl = (__nv_bfloat16*)sym(g_adjl);
    __nv_bfloat16* atth = (__nv_bfloat16*)sym(g_atth);
    __nv_bfloat16* attm = (__nv_bfloat16*)sym(g_attm);
    __nv_bfloat16* attl = (__nv_bfloat16*)sym(g_attl);
    __nv_bfloat16* qh = (__nv_bfloat16*)sym(g_qh);
    __nv_bfloat16* qm = (__nv_bfloat16*)sym(g_qm);
    __nv_bfloat16* ql = (__nv_bfloat16*)sym(g_ql);
    __nv_bfloat16* kh = (__nv_bfloat16*)sym(g_kh);
    __nv_bfloat16* km = (__nv_bfloat16*)sym(g_km);
    __nv_bfloat16* kl = (__nv_bfloat16*)sym(g_kl);
    __nv_bfloat16* xwTh = (__nv_bfloat16*)sym(g_xwTh);
    __nv_bfloat16* xwTm = (__nv_bfloat16*)sym(g_xwTm);
    __nv_bfloat16* xwTl = (__nv_bfloat16*)sym(g_xwTl);
    __nv_bfloat16* vTh = (__nv_bfloat16*)sym(g_vTh);
    __nv_bfloat16* vTm = (__nv_bfloat16*)sym(g_vTm);
    __nv_bfloat16* vTl = (__nv_bfloat16*)sym(g_vTl);

    cudaFuncSetAttribute(hmma_kernel<EPI_BIAS_RELU>,
                         cudaFuncAttributeMaxDynamicSharedMemorySize, HSMEM_BYTES);
    cudaFuncSetAttribute(hmma_kernel<EPI_RELU>,
                         cudaFuncAttributeMaxDynamicSharedMemorySize, HSMEM_BYTES);
    cudaFuncSetAttribute(hmma_kernel<EPI_MUL>,
                         cudaFuncAttributeMaxDynamicSharedMemorySize, HSMEM_BYTES);

    // 1. gating
    init_z123_kernel<<<(NV * 15 + 255) / 256, 256>>>(b_at1, b_at2, b_at3);
    gates_kernel<<<dim3(24, 24, 3), 256>>>(adj0, adj1, adj2, W_at1, W_at2, W_at3);
    nz_kernel<<<(NV + 255) / 256, 256>>>(W_agg, b_agg, out);

    // 2. combined adjacency (fp32 + bf16 triplet)
    combine_kernel<<<(unsigned)((size_t)NV * NV / 4 / 256), 256>>>(
        (const float4*)adj0, (const float4*)adj1, (const float4*)adj2);

    // 3. xw = x @ W_g1 (scalar), then transpose-split
    gemm_kernel<EPI_NONE, false><<<dim3(2, 48), 256>>>(x, W_g1, xwS, NV, NH, NF, NF, NH,
                                                       nullptr, nullptr);
    transpose_split_kernel<<<dim3(NV / 32, NH / 32), 256>>>(xwS, xwTh, xwTm, xwTl);

    // 4. h = relu(adj @ xw + b_g1)  [tensor]
    hmma_kernel<EPI_BIAS_RELU><<<dim3(2, 48), 512, HSMEM_BYTES>>>(
        adjh, adjm, adjl, xwTh, xwTm, xwTl, hS, NH, NV, b_g1, nullptr);

    // 5. Q, K, V (scalar) + splits
    gemm_kernel<EPI_BIAS, false><<<dim3(2, 48), 256>>>(hS, W_q, QS, NV, NH, NH, NH, NH, b_q, nullptr);
    gemm_kernel<EPI_BIAS, false><<<dim3(2, 48), 256>>>(hS, W_k, KS, NV, NH, NH, NH, NH, b_k, nullptr);
    gemm_kernel<EPI_BIAS, false><<<dim3(2, 48), 256>>>(hS, W_v, VS, NV, NH, NH, NH, NH, b_v, nullptr);
    split_kernel<<<(NV * NH + 255) / 256, 256>>>(QS, qh, qm, ql, NV * NH);
    split_kernel<<<(NV * NH + 255) / 256, 256>>>(KS, kh, km, kl, NV * NH);
    transpose_split_kernel<<<dim3(NV / 32, NH / 32), 256>>>(VS, vTh, vTm, vTl);

    // 6. A_tilde = adj * (Q @ K^T)  [tensor]
    hmma_kernel<EPI_MUL><<<dim3(48, 48), 512, HSMEM_BYTES>>>(
        qh, qm, ql, kh, km, kl, attS, NV, NH, nullptr, adjS);

    // 7. attention = softmax(A_tilde) -> bf16 triplet (gcn_norm == identity to ~1e-7)
    softmax_rows_kernel<<<NV, 256>>>(attS);

    // 8. X_tilde = relu(attention @ V)  [tensor]
    hmma_kernel<EPI_RELU><<<dim3(2, 48), 512, HSMEM_BYTES>>>(
        atth, attm, attl, vTh, vTm, vTl, XS, NH, NV, nullptr, nullptr);

    // 9. u = X_tilde @ W_g2 (scalar)
    gemm_kernel<EPI_NONE, false><<<dim3(1, 48), 256>>>(XS, W_g2, uS, NV, NC, NH, NH, NC,
                                                       nullptr, nullptr);
    // 10. z = adj @ u + b_g2 (k-split scalar)
    init_z_kernel<<<(NV * NC + 255) / 256, 256>>>(b_g2);
    gemm_n16_ksplit<<<dim3(48, 8), 256>>>(adjS, NV, uS, zS, NV / 8);

    // 11. out[:, :16] = softmax(z)
    softmax16_kernel<<<(NV + 255) / 256, 256>>>(zS, out);

    (void)in_sizes; (void)n_in; (void)out_size;
}

// round 12
// speedup vs baseline: 2.4080x; 1.5311x over previous
#include <cuda_runtime.h>
#include <cuda_bf16.h>
#include <math.h>
#include <stdint.h>

#define NV 6144
#define NF 512
#define NH 256
#define NC 16

typedef unsigned long long u64;
typedef __nv_bfloat16 bf16;

// ================= helpers =================
__device__ __forceinline__ u64 pack2(float lo, float hi) {
    u64 r; asm("mov.b64 %0, {%1, %2};" : "=l"(r) : "f"(lo), "f"(hi)); return r;
}
__device__ __forceinline__ void fma2(u64& d, u64 a, u64 b) {
    asm("fma.rn.f32x2 %0, %1, %2, %0;" : "+l"(d) : "l"(a), "l"(b));
}
__device__ __forceinline__ float2 unpack2(u64 v) {
    float2 r; asm("mov.b64 {%0, %1}, %2;" : "=f"(r.x), "=f"(r.y) : "l"(v)); return r;
}

// bf16 2-way split: a == h + m up to ~2^-17 relative
__device__ __forceinline__ void split2(float a, bf16& h, bf16& m) {
    h = __float2bfloat16(a);
    m = __float2bfloat16(a - __bfloat162float(h));
}
__device__ __forceinline__ float2 ldpair(const bf16* p) {
    return __bfloat1622float2(*(const __nv_bfloat162*)p);
}

__device__ __forceinline__ void mma_bf16(float* acc, const uint32_t* a, const uint32_t* b) {
    asm volatile(
        "mma.sync.aligned.m16n8k16.row.col.f32.bf16.bf16.f32 "
        "{%0,%1,%2,%3}, {%4,%5,%6,%7}, {%8,%9}, {%0,%1,%2,%3};\n"
        : "+f"(acc[0]), "+f"(acc[1]), "+f"(acc[2]), "+f"(acc[3])
        : "r"(a[0]), "r"(a[1]), "r"(a[2]), "r"(a[3]), "r"(b[0]), "r"(b[1]));
}
__device__ __forceinline__ u64 to_global(const void* p) {
    u64 g; asm("cvta.to.global.u64 %0, %1;" : "=l"(g) : "l"(p)); return g;
}
#define CP16(dst_u32, src_g) \
    asm volatile("cp.async.cg.shared.global [%0], [%1], 16;" \
                 :: "r"(dst_u32), "l"(src_g) : "memory")

// ================= scratch =================
__device__ float g_att[(size_t)NV * NV];   // A_tilde (pre-softmax)
__device__ float g_z123[NV * 15];
__device__ float g_nzT[3][NV];
__device__ float g_xw[NV * NH];
__device__ float g_V[NV * NH];
__device__ float g_X[NV * NH];
__device__ float g_u[NV * NC];
__device__ float g_z[NV * NC];
// bf16 split pairs
__device__ bf16 g_adjh[(size_t)NV * NV], g_adjm[(size_t)NV * NV];
__device__ bf16 g_atth[(size_t)NV * NV], g_attm[(size_t)NV * NV];
__device__ bf16 g_hh[NV * NH], g_hm[NV * NH];
__device__ bf16 g_qh[NV * NH], g_qm[NV * NH];
__device__ bf16 g_kh[NV * NH], g_km[NV * NH];
__device__ bf16 g_xh[NV * NF], g_xm[NV * NF];
__device__ bf16 g_xwTh[NH * NV], g_xwTm[NH * NV];
__device__ bf16 g_vTh[NH * NV], g_vTm[NH * NV];
__device__ bf16 g_wg1h[NF * NH], g_wg1m[NF * NH];
__device__ bf16 g_wqh[NH * NH], g_wqm[NH * NH];
__device__ bf16 g_wkh[NH * NH], g_wkm[NH * NH];
__device__ bf16 g_wvh[NH * NH], g_wvm[NH * NH];

// ================= gating pass =================
__global__ void init_z123_kernel(const float* __restrict__ b1, const float* __restrict__ b2,
                                 const float* __restrict__ b3) {
    int idx = blockIdx.x * blockDim.x + threadIdx.x;
    if (idx < NV * 15) {
        int f = idx % 15;
        int m = f / 5;
        const float* b = (m == 0) ? b1 : (m == 1) ? b2 : b3;
        g_z123[idx] = b[f % 5];
    }
}

__global__ __launch_bounds__(256) void gates_kernel(
    const float* __restrict__ a0, const float* __restrict__ a1, const float* __restrict__ a2,
    const float* __restrict__ W1, const float* __restrict__ W2, const float* __restrict__ W3) {
    int m = blockIdx.z;
    const float* A = (m == 0) ? a0 : (m == 1) ? a1 : a2;
    const float* W = (m == 0) ? W1 : (m == 1) ? W2 : W3;
    int warp = threadIdx.x >> 5;
    int lane = threadIdx.x & 31;
    int jbase = blockIdx.y * 256;
    int row0 = blockIdx.x * 256 + warp * 32;

    float w[8][5];
#pragma unroll
    for (int k = 0; k < 8; k++) {
        int j = jbase + k * 32 + lane;
#pragma unroll
        for (int f = 0; f < 5; f++) w[k][f] = W[j * 5 + f];
    }
    for (int r = 0; r < 32; r++) {
        int i = row0 + r;
        const float* arow = A + (size_t)i * NV + jbase;
        float ac0 = 0.f, ac1 = 0.f, ac2 = 0.f, ac3 = 0.f, ac4 = 0.f;
#pragma unroll
        for (int k = 0; k < 8; k++) {
            float a = arow[k * 32 + lane];
            ac0 = fmaf(a, w[k][0], ac0);
            ac1 = fmaf(a, w[k][1], ac1);
            ac2 = fmaf(a, w[k][2], ac2);
            ac3 = fmaf(a, w[k][3], ac3);
            ac4 = fmaf(a, w[k][4], ac4);
        }
#pragma unroll
        for (int off = 16; off > 0; off >>= 1) {
            ac0 += __shfl_xor_sync(0xffffffffu, ac0, off);
            ac1 += __shfl_xor_sync(0xffffffffu, ac1, off);
            ac2 += __shfl_xor_sync(0xffffffffu, ac2, off);
            ac3 += __shfl_xor_sync(0xffffffffu, ac3, off);
            ac4 += __shfl_xor_sync(0xffffffffu, ac4, off);
        }
        if (lane == 0) {
            float* zp = &g_z123[i * 15 + m * 5];
            atomicAdd(zp + 0, ac0);
            atomicAdd(zp + 1, ac1);
            atomicAdd(zp + 2, ac2);
            atomicAdd(zp + 3, ac3);
            atomicAdd(zp + 4, ac4);
        }
    }
}

__global__ void nz_kernel(const float* __restrict__ Wagg, const float* __restrict__ bagg,
                          float* __restrict__ out) {
    int i = blockIdx.x * blockDim.x + threadIdx.x;
    if (i >= NV) return;
    float zi[15];
#pragma unroll
    for (int f = 0; f < 15; f++) zi[f] = g_z123[i * 15 + f];
    float z4[3];
#pragma unroll
    for (int c = 0; c < 3; c++) {
        float s = bagg[c];
#pragma unroll
        for (int f = 0; f < 15; f++) s = fmaf(zi[f], Wagg[f * 3 + c], s);
        z4[c] = s;
    }
    float mx = fmaxf(z4[0], fmaxf(z4[1], z4[2]));
    float e0 = __expf(z4[0] - mx);
    float e1 = __expf(z4[1] - mx);
    float e2 = __expf(z4[2] - mx);
    float inv = 1.0f / (e0 + e1 + e2);
    float p0 = e0 * inv, p1 = e1 * inv, p2 = e2 * inv;
    g_nzT[0][i] = p0;
    g_nzT[1][i] = p1;
    g_nzT[2][i] = p2;
    out[NV * NC + i * 3 + 0] = p0;
    out[NV * NC + i * 3 + 1] = p1;
    out[NV * NC + i * 3 + 2] = p2;
}

// combined adjacency -> bf16 split pair only (no fp32 copy kept)
__global__ void combine_kernel(const float4* __restrict__ a0, const float4* __restrict__ a1,
                               const float4* __restrict__ a2) {
    size_t t = (size_t)blockIdx.x * blockDim.x + threadIdx.x;
    const size_t total = (size_t)NV * NV / 4;
    if (t >= total) return;
    int j4 = (int)(t % (NV / 4));
    const float4* n0 = (const float4*)g_nzT[0];
    const float4* n1 = (const float4*)g_nzT[1];
    const float4* n2 = (const float4*)g_nzT[2];
    float4 v0 = a0[t], v1 = a1[t], v2 = a2[t];
    float4 w0 = n0[j4], w1 = n1[j4], w2 = n2[j4];
    float4 r;
    r.x = fmaf(w0.x, v0.x, fmaf(w1.x, v1.x, w2.x * v2.x));
    r.y = fmaf(w0.y, v0.y, fmaf(w1.y, v1.y, w2.y * v2.y));
    r.z = fmaf(w0.z, v0.z, fmaf(w1.z, v1.z, w2.z * v2.z));
    r.w = fmaf(w0.w, v0.w, fmaf(w1.w, v1.w, w2.w * v2.w));
    __align__(8) bf16 hb[4], mb[4];
    split2(r.x, hb[0], mb[0]);
    split2(r.y, hb[1], mb[1]);
    split2(r.z, hb[2], mb[2]);
    split2(r.w, hb[3], mb[3]);
    *(uint2*)(g_adjh + 4 * t) = *(uint2*)hb;
    *(uint2*)(g_adjm + 4 * t) = *(uint2*)mb;
}

// elementwise fp32 -> bf16 pair
__global__ void split2_kernel(const float* __restrict__ s, bf16* __restrict__ h,
                              bf16* __restrict__ m, int n) {
    int i = blockIdx.x * blockDim.x + threadIdx.x;
    if (i < n) split2(s[i], h[i], m[i]);
}

// [R,C] fp32 -> transposed [C,R] bf16 pair: dst[c*R + r] = src[r*C + c]
__global__ __launch_bounds__(256) void tsplit2_kernel(
    const float* __restrict__ src, bf16* __restrict__ dh, bf16* __restrict__ dm,
    int R, int C) {
    __shared__ float t[32][33];
    int r0 = blockIdx.x * 32;
    int c0 = blockIdx.y * 32;
    int x = threadIdx.x & 31;
    int y = threadIdx.x >> 5;
    for (int yy = y; yy < 32; yy += 8)
        t[yy][x] = src[(size_t)(r0 + yy) * C + c0 + x];
    __syncthreads();
    for (int yy = y; yy < 32; yy += 8) {
        float v = t[x][yy];   // = src[r0+x][c0+yy]
        size_t o = (size_t)(c0 + yy) * R + r0 + x;
        bf16 h, m;
        split2(v, h, m);
        dh[o] = h; dm[o] = m;
    }
}

// ================= tensor-core split2 GEMM =================
// C[M, Nc] = A @ B^T with A (h,m) [M,Kc], B (h,m) [Nc,Kc]; 3 products hh,hm,mh.
// CTA tile 128x128, K-stage 64, 8 warps of 32x64, double-buffered cp.async.
#define EPI_NONE 0
#define EPI_BIAS 1
#define EPI_BIAS_RELU_SPL 2
#define EPI_BIAS_SPL 3
#define EPI_MUL2 4
#define EPI_RELU 5
#define SA 72
#define TILE_ELEMS (128 * SA)
#define TILE_BYTES (TILE_ELEMS * 2)   // 18432
#define BUF_BYTES (4 * TILE_BYTES)    // 73728
#define HSMEM_BYTES (2 * BUF_BYTES)   // 147456

template <int EPI>
__global__ __launch_bounds__(256, 1) void hmma_kernel(
    const bf16* __restrict__ Ah, const bf16* __restrict__ Am,
    const bf16* __restrict__ Bh, const bf16* __restrict__ Bm,
    float* __restrict__ C, bf16* __restrict__ Oh, bf16* __restrict__ Om,
    int Nc, int Kc, const float* __restrict__ bias,
    const bf16* __restrict__ Eh, const bf16* __restrict__ Em) {
    extern __shared__ __align__(16) char smem_raw[];
    const uint32_t smem_u32 = (uint32_t)__cvta_generic_to_shared(smem_raw);

    const int tid = threadIdx.x;
    const int wid = tid >> 5;
    const int lane = tid & 31;
    const int wm = wid >> 1;          // 0..3 (m block of 32)
    const int wn = wid & 1;           // 0..1 (n block of 64)
    const int m0 = blockIdx.y * 128;
    const int n0 = blockIdx.x * 128;
    const int lg = lane >> 2;
    const int lt = (lane & 3) * 2;

    u64 ga[2], gb[2];
    ga[0] = to_global(Ah); ga[1] = to_global(Am);
    gb[0] = to_global(Bh); gb[1] = to_global(Bm);

    float acc[2][8][4] = {};
    const int nstage = Kc >> 6;

    auto issue_stage = [&](int stage, int buf) {
        const int k0 = stage << 6;
#pragma unroll
        for (int it = 0; it < 4; it++) {
            int idx = it * 256 + tid;     // 0..1023
            int r = idx >> 3;
            int c8 = idx & 7;
            uint32_t soff = smem_u32 + buf * BUF_BYTES + (uint32_t)(r * SA + c8 * 8) * 2;
            u64 aoff = ((u64)(m0 + r) * Kc + k0 + c8 * 8) * 2;
            u64 boff = ((u64)(n0 + r) * Kc + k0 + c8 * 8) * 2;
#pragma unroll
            for (int t = 0; t < 2; t++) {
                CP16(soff + t * TILE_BYTES, ga[t] + aoff);
                CP16(soff + (2 + t) * TILE_BYTES, gb[t] + boff);
            }
        }
        asm volatile("cp.async.commit_group;" ::: "memory");
    };

    issue_stage(0, 0);

    for (int stage = 0; stage < nstage; stage++) {
        const int buf = stage & 1;
        if (stage + 1 < nstage) {
            issue_stage(stage + 1, (stage + 1) & 1);
            asm volatile("cp.async.wait_group 1;" ::: "memory");
        } else {
            asm volatile("cp.async.wait_group 0;" ::: "memory");
        }
        __syncthreads();

        const bf16* base = (const bf16*)smem_raw + buf * 4 * TILE_ELEMS;
        const bf16* As = base;
        const bf16* Bs = base + 2 * TILE_ELEMS;

#pragma unroll 1
        for (int k16 = 0; k16 < 4; k16++) {
            const int kb = k16 * 16 + lt;
            uint32_t bfr[2][8][2];
#pragma unroll
            for (int t = 0; t < 2; t++)
#pragma unroll
                for (int nt = 0; nt < 8; nt++) {
                    const bf16* bp = Bs + t * TILE_ELEMS + (wn * 64 + nt * 8 + lg) * SA + kb;
                    bfr[t][nt][0] = *(const uint32_t*)bp;
                    bfr[t][nt][1] = *(const uint32_t*)(bp + 8);
                }
            // g=0 (Ah): products with Bh, Bm; g=1 (Am): product with Bh
#pragma unroll
            for (int g = 0; g < 2; g++) {
                uint32_t afr[2][4];
#pragma unroll
                for (int mt = 0; mt < 2; mt++) {
                    const bf16* ap = As + g * TILE_ELEMS + (wm * 32 + mt * 16 + lg) * SA + kb;
                    afr[mt][0] = *(const uint32_t*)ap;
                    afr[mt][1] = *(const uint32_t*)(ap + 8 * SA);
                    afr[mt][2] = *(const uint32_t*)(ap + 8);
                    afr[mt][3] = *(const uint32_t*)(ap + 8 * SA + 8);
                }
                const int nb = (g == 0) ? 2 : 1;
#pragma unroll
                for (int b = 0; b < 2; b++) {
                    if (b < nb) {
#pragma unroll
                        for (int mt = 0; mt < 2; mt++)
#pragma unroll
                            for (int nt = 0; nt < 8; nt++)
                                mma_bf16(acc[mt][nt], afr[mt], bfr[b][nt]);
                    }
                }
            }
        }
        __syncthreads();
    }

    // ---- epilogue ----
#pragma unroll
    for (int mt = 0; mt < 2; mt++) {
#pragma unroll
        for (int nt = 0; nt < 8; nt++) {
            int c0 = n0 + wn * 64 + nt * 8 + lt;
#pragma unroll
            for (int half = 0; half < 2; half++) {
                int row = m0 + wm * 32 + mt * 16 + lg + half * 8;
                size_t base = (size_t)row * Nc + c0;
                float v0 = acc[mt][nt][half * 2 + 0];
                float v1 = acc[mt][nt][half * 2 + 1];
                if (EPI == EPI_BIAS || EPI == EPI_BIAS_RELU_SPL || EPI == EPI_BIAS_SPL) {
                    v0 += bias[c0];
                    v1 += bias[c0 + 1];
                }
                if (EPI == EPI_BIAS_RELU_SPL || EPI == EPI_RELU) {
                    v0 = fmaxf(v0, 0.f);
                    v1 = fmaxf(v1, 0.f);
                }
                if (EPI == EPI_MUL2) {
                    float2 eh = ldpair(Eh + base);
                    float2 em = ldpair(Em + base);
                    v0 *= (eh.x + em.x);
                    v1 *= (eh.y + em.y);
                }
                if (EPI == EPI_BIAS_RELU_SPL || EPI == EPI_BIAS_SPL) {
                    __align__(4) bf16 h[2], m[2];
                    split2(v0, h[0], m[0]);
                    split2(v1, h[1], m[1]);
                    *(uint32_t*)(Oh + base) = *(uint32_t*)h;
                    *(uint32_t*)(Om + base) = *(uint32_t*)m;
                } else {
                    *(float2*)(C + base) = make_float2(v0, v1);
                }
            }
        }
    }
}

// ================= scalar FFMA2 GEMM (u = X @ W_g2 only) =================
__global__ __launch_bounds__(256) void gemm_n16_kernel(
    const float* __restrict__ A, const float* __restrict__ B, float* __restrict__ C,
    int Kc) {
    __shared__ float As[16][128];
    __shared__ float Bs[16][16];
    int tid = threadIdx.x;
    int bm = blockIdx.y * 128;
    int tx = tid & 15;
    int ty = tid >> 4;
    float acc[8][2] = {};
    int arow = tid >> 1;
    int akk = (tid & 1) * 8;

    for (int k0 = 0; k0 < Kc; k0 += 16) {
        {
            const float* ap = A + (size_t)(bm + arow) * Kc + k0 + akk;
            float4 p0 = *(const float4*)ap;
            float4 p1 = *(const float4*)(ap + 4);
            As[akk + 0][arow] = p0.x; As[akk + 1][arow] = p0.y;
            As[akk + 2][arow] = p0.z; As[akk + 3][arow] = p0.w;
            As[akk + 4][arow] = p1.x; As[akk + 5][arow] = p1.y;
            As[akk + 6][arow] = p1.z; As[akk + 7][arow] = p1.w;
        }
        if (tid < 64) {
            int bkk = tid >> 2;
            int bc = (tid & 3) * 4;
            *(float4*)&Bs[bkk][bc] = *(const float4*)(B + (size_t)(k0 + bkk) * NC + bc);
        }
        __syncthreads();
#pragma unroll
        for (int kk = 0; kk < 16; kk++) {
            float b0 = Bs[kk][tx];
            float a[8];
            *(float4*)&a[0] = *(float4*)&As[kk][ty * 8];
            *(float4*)&a[4] = *(float4*)&As[kk][ty * 8 + 4];
#pragma unroll
            for (int i = 0; i < 8; i++) acc[i][0] = fmaf(a[i], b0, acc[i][0]);
        }
        __syncthreads();
    }
#pragma unroll
    for (int i = 0; i < 8; i++)
        C[(size_t)(bm + ty * 8 + i) * NC + tx] = acc[i][0];
}

// ================= row softmax + att split-pair output =================
__global__ __launch_bounds__(256) void softmax_rows_kernel(const float* __restrict__ buf) {
    int row = blockIdx.x;
    const float* p = buf + (size_t)row * NV;
    int tid = threadIdx.x;
    int lane = tid & 31, wid = tid >> 5;
    __shared__ float red[8];
    __shared__ float red2[8];

    float v[24];
    float mx = -3.0e38f;
#pragma unroll
    for (int t = 0; t < 24; t++) {
        v[t] = p[t * 256 + tid];
        mx = fmaxf(mx, v[t]);
    }
#pragma unroll
    for (int off = 16; off > 0; off >>= 1) mx = fmaxf(mx, __shfl_xor_sync(0xffffffffu, mx, off));
    if (lane == 0) red[wid] = mx;
    __syncthreads();
    float rowmax = red[0];
#pragma unroll
    for (int w = 1; w < 8; w++) rowmax = fmaxf(rowmax, red[w]);

    float s = 0.f;
#pragma unroll
    for (int t = 0; t < 24; t++) {
        v[t] = __expf(v[t] - rowmax);
        s += v[t];
    }
#pragma unroll
    for (int off = 16; off > 0; off >>= 1) s += __shfl_xor_sync(0xffffffffu, s, off);
    if (lane == 0) red2[wid] = s;
    __syncthreads();
    float tot = 0.f;
#pragma unroll
    for (int w = 0; w < 8; w++) tot += red2[w];
    float inv = 1.0f / tot;
#pragma unroll
    for (int t = 0; t < 24; t++) {
        float val = v[t] * inv;
        size_t o = (size_t)row * NV + t * 256 + tid;
        bf16 h, m;
        split2(val, h, m);
        g_atth[o] = h;
        g_attm[o] = m;
    }
}

// ================= final stage: z = adj @ u + b_g2 (adj from bf16 pair) ============
__global__ void init_z_kernel(const float* __restrict__ bg2) {
    int idx = blockIdx.x * blockDim.x + threadIdx.x;
    if (idx < NV * NC) g_z[idx] = bg2[idx % NC];
}

__global__ __launch_bounds__(256) void gemm_n16_ksplit(const bf16* __restrict__ Ahp,
                                                       const bf16* __restrict__ Amp,
                                                       const float* __restrict__ Bm,
                                                       float* __restrict__ C, int Kchunk) {
    __shared__ float As[64][128];
    __shared__ float Bs[64][16];
    int tid = threadIdx.x;
    int bm = blockIdx.x * 128;
    int k0base = blockIdx.y * Kchunk;
    int col = tid & 15;
    int rowg = tid >> 4;
    float acc[8] = {};
    int arow = tid >> 1;
    int ak0 = (tid & 1) * 32;
    int bk = tid >> 2;
    int bc4 = (tid & 3) * 4;

    for (int k0 = k0base; k0 < k0base + Kchunk; k0 += 64) {
        float4 bv = *(const float4*)(Bm + (size_t)(k0 + bk) * 16 + bc4);
        *(float4*)&Bs[bk][bc4] = bv;
        size_t aoff = (size_t)(bm + arow) * NV + k0 + ak0;
        const __nv_bfloat162* hp = (const __nv_bfloat162*)(Ahp + aoff);
        const __nv_bfloat162* mp = (const __nv_bfloat162*)(Amp + aoff);
#pragma unroll
        for (int c = 0; c < 16; c++) {
            float2 hv = __bfloat1622float2(hp[c]);
            float2 mv = __bfloat1622float2(mp[c]);
            As[ak0 + 2 * c + 0][arow] = hv.x + mv.x;
            As[ak0 + 2 * c + 1][arow] = hv.y + mv.y;
        }
        __syncthreads();
#pragma unroll 8
        for (int kk = 0; kk < 64; kk++) {
            float b = Bs[kk][col];
#pragma unroll
            for (int i = 0; i < 8; i++) acc[i] = fmaf(As[kk][rowg * 8 + i], b, acc[i]);
        }
        __syncthreads();
    }
#pragma unroll
    for (int i = 0; i < 8; i++)
        atomicAdd(&C[(size_t)(bm + rowg * 8 + i) * NC + col], acc[i]);
}

__global__ void softmax16_kernel(const float* __restrict__ z, float* __restrict__ out) {
    int i = blockIdx.x * blockDim.x + threadIdx.x;
    if (i >= NV) return;
    float v[NC];
    float mx = -3.0e38f;
#pragma unroll
    for (int c = 0; c < NC; c++) {
        v[c] = z[i * NC + c];
        mx = fmaxf(mx, v[c]);
    }
    float s = 0.f;
#pragma unroll
    for (int c = 0; c < NC; c++) {
        v[c] = __expf(v[c] - mx);
        s += v[c];
    }
    float inv = 1.0f / s;
#pragma unroll
    for (int c = 0; c < NC; c++) out[i * NC + c] = v[c] * inv;
}

// ================= host orchestration =================
static void* sym(const void* s) { void* p; cudaGetSymbolAddress(&p, s); return p; }

extern "C" void kernel_launch(void* const* d_in, const int* in_sizes, int n_in,
                              void* d_out, int out_size) {
    const float* adj0 = (const float*)d_in[0];
    const float* adj1 = (const float*)d_in[1];
    const float* adj2 = (const float*)d_in[2];
    const float* x = (const float*)d_in[3];
    const float* W_at1 = (const float*)d_in[4];
    const float* b_at1 = (const float*)d_in[5];
    const float* W_at2 = (const float*)d_in[6];
    const float* b_at2 = (const float*)d_in[7];
    const float* W_at3 = (const float*)d_in[8];
    const float* b_at3 = (const float*)d_in[9];
    const float* W_agg = (const float*)d_in[10];
    const float* b_agg = (const float*)d_in[11];
    const float* W_g1 = (const float*)d_in[12];
    const float* b_g1 = (const float*)d_in[13];
    const float* W_g2 = (const float*)d_in[14];
    const float* b_g2 = (const float*)d_in[15];
    const float* W_q = (const float*)d_in[16];
    const float* b_q = (const float*)d_in[17];
    const float* W_k = (const float*)d_in[18];
    const float* b_k = (const float*)d_in[19];
    const float* W_v = (const float*)d_in[20];
    const float* b_v = (const float*)d_in[21];
    float* out = (float*)d_out;

    float* attS = (float*)sym(g_att);
    float* xwS = (float*)sym(g_xw);
    float* VS = (float*)sym(g_V);
    float* XS = (float*)sym(g_X);
    float* uS = (float*)sym(g_u);
    float* zS = (float*)sym(g_z);
    bf16* adjh = (bf16*)sym(g_adjh); bf16* adjm = (bf16*)sym(g_adjm);
    bf16* atth = (bf16*)sym(g_atth); bf16* attm = (bf16*)sym(g_attm);
    bf16* hh = (bf16*)sym(g_hh);     bf16* hm = (bf16*)sym(g_hm);
    bf16* qh = (bf16*)sym(g_qh);     bf16* qm = (bf16*)sym(g_qm);
    bf16* kh = (bf16*)sym(g_kh);     bf16* km = (bf16*)sym(g_km);
    bf16* xh = (bf16*)sym(g_xh);     bf16* xm = (bf16*)sym(g_xm);
    bf16* xwTh = (bf16*)sym(g_xwTh); bf16* xwTm = (bf16*)sym(g_xwTm);
    bf16* vTh = (bf16*)sym(g_vTh);   bf16* vTm = (bf16*)sym(g_vTm);
    bf16* wg1h = (bf16*)sym(g_wg1h); bf16* wg1m = (bf16*)sym(g_wg1m);
    bf16* wqh = (bf16*)sym(g_wqh);   bf16* wqm = (bf16*)sym(g_wqm);
    bf16* wkh = (bf16*)sym(g_wkh);   bf16* wkm = (bf16*)sym(g_wkm);
    bf16* wvh = (bf16*)sym(g_wvh);   bf16* wvm = (bf16*)sym(g_wvm);

    cudaFuncSetAttribute(hmma_kernel<EPI_NONE>, cudaFuncAttributeMaxDynamicSharedMemorySize, HSMEM_BYTES);
    cudaFuncSetAttribute(hmma_kernel<EPI_BIAS>, cudaFuncAttributeMaxDynamicSharedMemorySize, HSMEM_BYTES);
    cudaFuncSetAttribute(hmma_kernel<EPI_BIAS_RELU_SPL>, cudaFuncAttributeMaxDynamicSharedMemorySize, HSMEM_BYTES);
    cudaFuncSetAttribute(hmma_kernel<EPI_BIAS_SPL>, cudaFuncAttributeMaxDynamicSharedMemorySize, HSMEM_BYTES);
    cudaFuncSetAttribute(hmma_kernel<EPI_MUL2>, cudaFuncAttributeMaxDynamicSharedMemorySize, HSMEM_BYTES);
    cudaFuncSetAttribute(hmma_kernel<EPI_RELU>, cudaFuncAttributeMaxDynamicSharedMemorySize, HSMEM_BYTES);

    // 1. gating
    init_z123_kernel<<<(NV * 15 + 255) / 256, 256>>>(b_at1, b_at2, b_at3);
    gates_kernel<<<dim3(24, 24, 3), 256>>>(adj0, adj1, adj2, W_at1, W_at2, W_at3);
    nz_kernel<<<(NV + 255) / 256, 256>>>(W_agg, b_agg, out);

    // 2. combined adjacency -> bf16 pair
    combine_kernel<<<(unsigned)((size_t)NV * NV / 4 / 256), 256>>>(
        (const float4*)adj0, (const float4*)adj1, (const float4*)adj2);

    // 3. input/weight splits
    split2_kernel<<<(NV * NF + 255) / 256, 256>>>(x, xh, xm, NV * NF);
    tsplit2_kernel<<<dim3(NF / 32, NH / 32), 256>>>(W_g1, wg1h, wg1m, NF, NH);
    tsplit2_kernel<<<dim3(NH / 32, NH / 32), 256>>>(W_q, wqh, wqm, NH, NH);
    tsplit2_kernel<<<dim3(NH / 32, NH / 32), 256>>>(W_k, wkh, wkm, NH, NH);
    tsplit2_kernel<<<dim3(NH / 32, NH / 32), 256>>>(W_v, wvh, wvm, NH, NH);

    // 4. xw = x @ W_g1  [tensor]
    hmma_kernel<EPI_NONE><<<dim3(2, 48), 256, HSMEM_BYTES>>>(
        xh, xm, wg1h, wg1m, xwS, nullptr, nullptr, NH, NF, nullptr, nullptr, nullptr);
    tsplit2_kernel<<<dim3(NV / 32, NH / 32), 256>>>(xwS, xwTh, xwTm, NV, NH);

    // 5. h = relu(adj @ xw + b_g1) -> split pair directly  [tensor]
    hmma_kernel<EPI_BIAS_RELU_SPL><<<dim3(2, 48), 256, HSMEM_BYTES>>>(
        adjh, adjm, xwTh, xwTm, nullptr, hh, hm, NH, NV, b_g1, nullptr, nullptr);

    // 6. Q, K (split-pair out), V (fp32)  [tensor]
    hmma_kernel<EPI_BIAS_SPL><<<dim3(2, 48), 256, HSMEM_BYTES>>>(
        hh, hm, wqh, wqm, nullptr, qh, qm, NH, NH, b_q, nullptr, nullptr);
    hmma_kernel<EPI_BIAS_SPL><<<dim3(2, 48), 256, HSMEM_BYTES>>>(
        hh, hm, wkh, wkm, nullptr, kh, km, NH, NH, b_k, nullptr, nullptr);
    hmma_kernel<EPI_BIAS><<<dim3(2, 48), 256, HSMEM_BYTES>>>(
        hh, hm, wvh, wvm, VS, nullptr, nullptr, NH, NH, b_v, nullptr, nullptr);
    tsplit2_kernel<<<dim3(NV / 32, NH / 32), 256>>>(VS, vTh, vTm, NV, NH);

    // 7. A_tilde = adj * (Q @ K^T)  [tensor, adj from bf16 pair]
    hmma_kernel<EPI_MUL2><<<dim3(48, 48), 256, HSMEM_BYTES>>>(
        qh, qm, kh, km, attS, nullptr, nullptr, NV, NH, nullptr, adjh, adjm);

    // 8. attention = softmax(A_tilde) -> bf16 pair (gcn_norm == identity to ~1e-7)
    softmax_rows_kernel<<<NV, 256>>>(attS);

    // 9. X_tilde = relu(attention @ V)  [tensor]
    hmma_kernel<EPI_RELU><<<dim3(2, 48), 256, HSMEM_BYTES>>>(
        atth, attm, vTh, vTm, XS, nullptr, nullptr, NH, NV, nullptr, nullptr, nullptr);

    // 10. u = X_tilde @ W_g2 (scalar fp32)
    gemm_n16_kernel<<<dim3(1, 48), 256>>>(XS, W_g2, uS, NH);

    // 11. z = adj @ u + b_g2 (k-split, adj reconstructed from bf16 pair)
    init_z_kernel<<<(NV * NC + 255) / 256, 256>>>(b_g2);
    gemm_n16_ksplit<<<dim3(48, 8), 256>>>(adjh, adjm, uS, zS, NV / 8);

    // 12. out[:, :16] = softmax(z)
    softmax16_kernel<<<(NV + 255) / 256, 256>>>(zS, out);

    (void)in_sizes; (void)n_in; (void)out_size;
}